// round 14
// baseline (speedup 1.0000x reference)
#include <cuda_runtime.h>
#include <cuda_bf16.h>
#include <math.h>
#include <stdint.h>

// ---------------- problem constants ----------------
#define NN   10000
#define EE   160000
#define GGG  64
#define DDIM 480
#define HH   4
#define LLAY 6
#define DHH  120
#define NBB  128
#define SHN  9
#define QKVS 1440

static const float AVG_DEG_F   = 15.57930850982666f;
static const float AVG_NODES_F = 18.03065905448718f;

// ---------------- scratch buffer (static device memory) ---------------------
constexpr size_t SZ_SH   = (size_t)EE * SHN;
constexpr size_t SZ_RBF  = (size_t)EE * NBB;
constexpr size_t SZ_G0   = (size_t)EE;
constexpr size_t SZ_GATE = (size_t)LLAY * EE * HH;
constexpr size_t SZ_ND   = (size_t)NN * DDIM;
constexpr size_t SZ_HID  = (size_t)NN * 2 * DDIM;
constexpr size_t SZ_LOG  = (size_t)EE * HH;
constexpr size_t SZ_NH   = (size_t)NN * HH;
constexpr size_t SZ_EH   = (size_t)EE * 64;

constexpr size_t O_SH   = 0;
constexpr size_t O_RBF  = O_SH   + SZ_SH;
constexpr size_t O_G0   = O_RBF  + SZ_RBF;
constexpr size_t O_GATE = O_G0   + SZ_G0;
constexpr size_t O_X    = O_GATE + SZ_GATE;
constexpr size_t O_QKV  = O_X    + SZ_ND;            // NN x 1440 (q|k|v rows)
constexpr size_t O_AGG  = O_QKV  + (size_t)NN * QKVS;
constexpr size_t O_TMP  = O_AGG  + SZ_ND;
constexpr size_t O_HN   = O_TMP  + SZ_ND;
constexpr size_t O_HID  = O_HN   + SZ_ND;
constexpr size_t O_LOG  = O_HID  + SZ_HID;
constexpr size_t O_M    = O_LOG  + SZ_LOG;
constexpr size_t O_DEN  = O_M    + SZ_NH;
constexpr size_t O_EH1  = O_DEN  + SZ_NH;
constexpr size_t O_EH2  = O_EH1  + SZ_EH;
constexpr size_t TOTAL_F = O_EH2 + SZ_EH;

__device__ float g_buf[TOTAL_F];

// fused qkv weights: (LLAY, 480, 1440)
__device__ float g_wqkv[(size_t)LLAY * DDIM * QKVS];

// ---------------- helpers ----------------
__device__ __forceinline__ float warpSum(float v) {
#pragma unroll
    for (int o = 16; o; o >>= 1) v += __shfl_down_sync(0xffffffffu, v, o);
    return v;
}

__device__ __forceinline__ float siluf(float x) {
    return x / (1.0f + expf(-x));
}

__device__ __forceinline__ void atomicMaxFloat(float* addr, float val) {
    int old = __float_as_int(*addr);
    while (__int_as_float(old) < val) {
        int prev = atomicCAS((int*)addr, old, __float_as_int(val));
        if (prev == old) break;
        old = prev;
    }
}

// Fast hi/lo bf16 split of a float pair using the packed converter.
// Bit-identical to per-value __float2bfloat16_rn splitting.
__device__ __forceinline__ void split_pack(float v0, float v1,
                                           uint32_t& uhi, uint32_t& ulo) {
    __nv_bfloat162 h = __float22bfloat162_rn(make_float2(v0, v1)); // .x lo16, .y hi16
    uhi = *reinterpret_cast<uint32_t*>(&h);
    float hf0 = __uint_as_float(uhi << 16);           // bf16(v0) as f32
    float hf1 = __uint_as_float(uhi & 0xffff0000u);   // bf16(v1) as f32
    __nv_bfloat162 l = __float22bfloat162_rn(make_float2(v0 - hf0, v1 - hf1));
    ulo = *reinterpret_cast<uint32_t*>(&l);
}

__device__ __forceinline__ void mma_bf16(float& c0, float& c1, float& c2, float& c3,
                                         uint32_t a0, uint32_t a1, uint32_t a2, uint32_t a3,
                                         uint32_t b0, uint32_t b1) {
    asm volatile(
        "mma.sync.aligned.m16n8k16.row.col.f32.bf16.bf16.f32 "
        "{%0,%1,%2,%3}, {%4,%5,%6,%7}, {%8,%9}, {%0,%1,%2,%3};\n"
        : "+f"(c0), "+f"(c1), "+f"(c2), "+f"(c3)
        : "r"(a0), "r"(a1), "r"(a2), "r"(a3), "r"(b0), "r"(b1));
}

// ---------------- pack Wq|Wk|Wv -> (L, 480, 1440) ---------------------------
__global__ void packqkv_kernel(const float* __restrict__ Wq,
                               const float* __restrict__ Wk,
                               const float* __restrict__ Wv,
                               float* __restrict__ W) {
    long long idx = (long long)blockIdx.x * blockDim.x + threadIdx.x;
    long long tot = (long long)LLAY * DDIM * QKVS;
    if (idx >= tot) return;
    int c = (int)(idx % QKVS);
    long long t = idx / QKVS;
    int k = (int)(t % DDIM);
    int l = (int)(t / DDIM);
    const float* src = (c < DDIM) ? Wq : (c < 2 * DDIM) ? Wk : Wv;
    W[idx] = src[((size_t)l * DDIM + k) * DDIM + (c % DDIM)];
}

// ---------------- edge geometry: sh (E,9) + rbf (E,128) -------------------
__global__ void edge_geom_kernel(const float* __restrict__ pos,
                                 const int* __restrict__ src,
                                 const int* __restrict__ dst,
                                 float* __restrict__ sh,
                                 float* __restrict__ rbf) {
    int e = (blockIdx.x * blockDim.x + threadIdx.x) >> 5;
    int lane = threadIdx.x & 31;
    if (e >= EE) return;
    int s = src[e], d = dst[e];
    float vx = pos[s * 3 + 0] - pos[d * 3 + 0];
    float vy = pos[s * 3 + 1] - pos[d * 3 + 1];
    float vz = pos[s * 3 + 2] - pos[d * 3 + 2];
    float r = sqrtf(vx * vx + vy * vy + vz * vz);
    float rr = r + 1e-12f;
    float x = vx / rr, y = vy / rr, z = vz / rr;
    if (lane == 0) {
        const float s3 = 1.7320508075688772f;
        const float s5 = 2.23606797749979f;
        const float s15 = 3.872983346207417f;
        float* o = sh + (size_t)e * SHN;
        o[0] = 1.0f;
        o[1] = s3 * x;
        o[2] = s3 * y;
        o[3] = s3 * z;
        o[4] = s15 * x * y;
        o[5] = s15 * y * z;
        o[6] = 0.5f * s5 * (3.0f * z * z - 1.0f);
        o[7] = s15 * x * z;
        o[8] = 0.5f * s15 * (x * x - y * y);
    }
    const float width = 5.0f / 128.0f;
    const float cstep = 5.0f / 127.0f;
#pragma unroll
    for (int t = 0; t < 4; t++) {
        int i = t * 32 + lane;
        float c = cstep * (float)i;
        float u = (r - c) / width;
        rbf[(size_t)e * NBB + i] = expf(-u * u);
    }
}

// ---------------- bf16x3 tensor-core GEMM (R3 verbatim) ---------------------
#define BM 128
#define BN 64
#define BK 32
#define K2T (BK / 2)
#define ASTR 136
#define BSTR 72

__global__ __launch_bounds__(256) void gemm_bf16x3_kernel(
    const float* __restrict__ A, const float* __restrict__ B,
    float* __restrict__ C, int M, int Ncol, int K, float alpha, int act) {
    __shared__ uint32_t As_hi[K2T][ASTR];
    __shared__ uint32_t As_lo[K2T][ASTR];
    __shared__ uint32_t Bs_hi[K2T][BSTR];
    __shared__ uint32_t Bs_lo[K2T][BSTR];

    const int tid = threadIdx.x;
    const int lane = tid & 31;
    const int w = tid >> 5;
    const int warpM = w & 3;
    const int warpN = w >> 2;
    const int gid = lane >> 2;
    const int tig = lane & 3;

    const int rowBase = blockIdx.y * BM;
    const int colBase = blockIdx.x * BN;

    float c[2][4][4];
#pragma unroll
    for (int mt = 0; mt < 2; mt++)
#pragma unroll
        for (int nt = 0; nt < 4; nt++)
#pragma unroll
            for (int i = 0; i < 4; i++) c[mt][nt][i] = 0.f;

    const int ar = tid >> 3;          // 0..31
    const int ac = (tid & 7) * 4;     // 0,4,...,28
    const int bk2 = tid >> 4;         // 0..15
    const int bn = (tid & 15) * 4;

    for (int kb = 0; kb < K; kb += BK) {
#pragma unroll
        for (int half = 0; half < 4; half++) {
            int rr = ar + half * 32;
            int gr = rowBase + rr;
            float4 av = make_float4(0.f, 0.f, 0.f, 0.f);
            if (gr < M) av = *(const float4*)&A[(size_t)gr * K + kb + ac];
            uint32_t uh, ul;
            split_pack(av.x, av.y, uh, ul);
            As_hi[(ac >> 1) + 0][rr] = uh;
            As_lo[(ac >> 1) + 0][rr] = ul;
            split_pack(av.z, av.w, uh, ul);
            As_hi[(ac >> 1) + 1][rr] = uh;
            As_lo[(ac >> 1) + 1][rr] = ul;
        }
        {
            int gc = colBase + bn;
            float4 b0 = make_float4(0.f, 0.f, 0.f, 0.f);
            float4 b1 = make_float4(0.f, 0.f, 0.f, 0.f);
            if (gc < Ncol) {
                b0 = *(const float4*)&B[(size_t)(kb + 2 * bk2) * Ncol + gc];
                b1 = *(const float4*)&B[(size_t)(kb + 2 * bk2 + 1) * Ncol + gc];
            }
            const float v0[4] = {b0.x, b0.y, b0.z, b0.w};
            const float v1[4] = {b1.x, b1.y, b1.z, b1.w};
#pragma unroll
            for (int j = 0; j < 4; j++) {
                uint32_t uh, ul;
                split_pack(v0[j], v1[j], uh, ul);
                Bs_hi[bk2][bn + j] = uh;
                Bs_lo[bk2][bn + j] = ul;
            }
        }
        __syncthreads();

#pragma unroll
        for (int ks = 0; ks < 2; ks++) {
            const int k2b = ks * 8;
            uint32_t ah[2][4], al[2][4], bh[4][2], bl[4][2];
#pragma unroll
            for (int mt = 0; mt < 2; mt++) {
                int m = warpM * 32 + mt * 16 + gid;
                ah[mt][0] = As_hi[k2b + tig][m];
                ah[mt][1] = As_hi[k2b + tig][m + 8];
                ah[mt][2] = As_hi[k2b + tig + 4][m];
                ah[mt][3] = As_hi[k2b + tig + 4][m + 8];
                al[mt][0] = As_lo[k2b + tig][m];
                al[mt][1] = As_lo[k2b + tig][m + 8];
                al[mt][2] = As_lo[k2b + tig + 4][m];
                al[mt][3] = As_lo[k2b + tig + 4][m + 8];
            }
#pragma unroll
            for (int nt = 0; nt < 4; nt++) {
                int n = warpN * 32 + nt * 8 + gid;
                bh[nt][0] = Bs_hi[k2b + tig][n];
                bh[nt][1] = Bs_hi[k2b + tig + 4][n];
                bl[nt][0] = Bs_lo[k2b + tig][n];
                bl[nt][1] = Bs_lo[k2b + tig + 4][n];
            }
#pragma unroll
            for (int mt = 0; mt < 2; mt++)
#pragma unroll
                for (int nt = 0; nt < 4; nt++) {
                    mma_bf16(c[mt][nt][0], c[mt][nt][1], c[mt][nt][2], c[mt][nt][3],
                             ah[mt][0], ah[mt][1], ah[mt][2], ah[mt][3],
                             bh[nt][0], bh[nt][1]);
                    mma_bf16(c[mt][nt][0], c[mt][nt][1], c[mt][nt][2], c[mt][nt][3],
                             ah[mt][0], ah[mt][1], ah[mt][2], ah[mt][3],
                             bl[nt][0], bl[nt][1]);
                    mma_bf16(c[mt][nt][0], c[mt][nt][1], c[mt][nt][2], c[mt][nt][3],
                             al[mt][0], al[mt][1], al[mt][2], al[mt][3],
                             bh[nt][0], bh[nt][1]);
                }
        }
        __syncthreads();
    }

#pragma unroll
    for (int mt = 0; mt < 2; mt++) {
#pragma unroll
        for (int nt = 0; nt < 4; nt++) {
            int gr0 = rowBase + warpM * 32 + mt * 16 + gid;
            int gc0 = colBase + warpN * 32 + nt * 8 + 2 * tig;
#pragma unroll
            for (int i = 0; i < 4; i++) {
                int gr = gr0 + (i >> 1) * 8;
                int gc = gc0 + (i & 1);
                if (gr < M && gc < Ncol) {
                    float v = c[mt][nt][i] * alpha;
                    if (act) v = siluf(v);
                    C[(size_t)gr * Ncol + gc] = v;
                }
            }
        }
    }
}

// -------------- MLP third layer: out(E,OD) = H2(E,64) @ W3(64,OD) ----------
__global__ void mlp3_kernel(const float* __restrict__ H2,
                            const float* __restrict__ W3,
                            float* __restrict__ out, int OD) {
    int e = (blockIdx.x * blockDim.x + threadIdx.x) >> 5;
    int lane = threadIdx.x & 31;
    if (e >= EE) return;
    float v0 = H2[(size_t)e * 64 + lane];
    float v1 = H2[(size_t)e * 64 + lane + 32];
    for (int o = 0; o < OD; o++) {
        float p = v0 * W3[lane * OD + o] + v1 * W3[(lane + 32) * OD + o];
        p = warpSum(p);
        if (lane == 0) out[(size_t)e * OD + o] = p;
    }
}

// -------------- x = atom_table[node_atom] ----------------------------------
__global__ void embed_kernel(const float* __restrict__ atom_table,
                             const int* __restrict__ node_atom,
                             float* __restrict__ x) {
    int i = blockIdx.x * blockDim.x + threadIdx.x;
    if (i >= NN * DDIM) return;
    int n = i / DDIM, dd = i - n * DDIM;
    x[i] = atom_table[node_atom[n] * DDIM + dd];
}

// -------------- x += (sh@Wdeg)*g0 / sqrt(AVG_DEG), scattered to dst --------
__global__ void deg_kernel(const float* __restrict__ sh,
                           const float* __restrict__ Wdeg,
                           const float* __restrict__ g0,
                           const int* __restrict__ dst,
                           float* __restrict__ x, float scale) {
    int e = (blockIdx.x * blockDim.x + threadIdx.x) >> 5;
    int lane = threadIdx.x & 31;
    if (e >= EE) return;
    int d = dst[e];
    float shreg[SHN];
#pragma unroll
    for (int i = 0; i < SHN; i++) shreg[i] = sh[(size_t)e * SHN + i];
    float g = g0[e] * scale;
#pragma unroll
    for (int t = 0; t < 15; t++) {
        int dd = t * 32 + lane;
        float val = 0.f;
#pragma unroll
        for (int si = 0; si < SHN; si++) val += shreg[si] * Wdeg[si * DDIM + dd];
        atomicAdd(&x[(size_t)d * DDIM + dd], val * g);
    }
}

// -------------- per-layer init: agg=0, m=-inf, den=0 -----------------------
__global__ void init_layer_kernel(float* __restrict__ agg,
                                  float* __restrict__ m,
                                  float* __restrict__ den) {
    int i = blockIdx.x * blockDim.x + threadIdx.x;
    if (i < NN * DDIM) agg[i] = 0.f;
    if (i < NN * HH) {
        m[i] = __int_as_float(0xff800000);
        den[i] = 0.f;
    }
}

// -------------- logits[e,h] = inv*gate * q[dst]·(k[src]+sh@Wsh) ------------
// q/k/v packed: row n = qkv[n*1440]; q at +0, k at +480, v at +960.
__global__ void logits_kernel(const float* __restrict__ qkv,
                              const float* __restrict__ sh,
                              const float* __restrict__ Wsh_l,
                              const float* __restrict__ gate_l,
                              const int* __restrict__ src,
                              const int* __restrict__ dst,
                              float* __restrict__ logits,
                              float* __restrict__ m) {
    int e = (blockIdx.x * blockDim.x + threadIdx.x) >> 5;
    int lane = threadIdx.x & 31;
    if (e >= EE) return;
    int s = src[e], d = dst[e];
    float shreg[SHN];
#pragma unroll
    for (int i = 0; i < SHN; i++) shreg[i] = sh[(size_t)e * SHN + i];
    const float* qrow = qkv + (size_t)d * QKVS;
    const float* krow = qkv + (size_t)s * QKVS + DDIM;
    const float inv = 0.09128709291752768f;
#pragma unroll
    for (int h = 0; h < HH; h++) {
        float acc = 0.f;
#pragma unroll
        for (int t = 0; t < 4; t++) {
            int j = t * 32 + lane;
            if (j < DHH) {
                int dd = h * DHH + j;
                float kv = krow[dd];
                float shk = 0.f;
#pragma unroll
                for (int si = 0; si < SHN; si++) shk += shreg[si] * Wsh_l[si * DDIM + dd];
                acc += qrow[dd] * (kv + shk);
            }
        }
        acc = warpSum(acc);
        if (lane == 0) {
            float lg = acc * inv * gate_l[(size_t)e * HH + h];
            logits[(size_t)e * HH + h] = lg;
            atomicMaxFloat(&m[(size_t)d * HH + h], lg);
        }
    }
}

// -------------- a = exp(logit - m[dst]); den[dst] += a ----------------------
__global__ void expden_kernel(float* __restrict__ logits,
                              const float* __restrict__ m,
                              float* __restrict__ den,
                              const int* __restrict__ dst) {
    int i = blockIdx.x * blockDim.x + threadIdx.x;
    if (i >= EE * HH) return;
    int e = i >> 2, h = i & 3;
    int d = dst[e];
    float a = expf(logits[i] - m[d * HH + h]);
    logits[i] = a;
    atomicAdd(&den[d * HH + h], a);
}

// -------------- agg[dst] += (a/den) * v[src] --------------------------------
__global__ void scatter_kernel(const float* __restrict__ a,
                               const float* __restrict__ den,
                               const float* __restrict__ qkv,
                               const int* __restrict__ src,
                               const int* __restrict__ dst,
                               float* __restrict__ agg) {
    int e = (blockIdx.x * blockDim.x + threadIdx.x) >> 5;
    int lane = threadIdx.x & 31;
    if (e >= EE) return;
    int s = src[e], d = dst[e];
    float al[HH];
#pragma unroll
    for (int h = 0; h < HH; h++)
        al[h] = a[(size_t)e * HH + h] / (den[(size_t)d * HH + h] + 1e-12f);
    const float* vrow = qkv + (size_t)s * QKVS + 2 * DDIM;
    float* arow = agg + (size_t)d * DDIM;
#pragma unroll
    for (int t = 0; t < 15; t++) {
        int dd = t * 32 + lane;
        int h = dd / DHH;
        atomicAdd(&arow[dd], al[h] * vrow[dd]);
    }
}

// -------------- x = LayerNorm(x + y), row length 480 ------------------------
__global__ void ln_residual_kernel(float* __restrict__ x,
                                   const float* __restrict__ y) {
    int n = blockIdx.x;
    int tid = threadIdx.x;  // 128
    size_t base = (size_t)n * DDIM;
    float v[4];
    float s = 0.f;
#pragma unroll
    for (int t = 0; t < 4; t++) {
        int dd = tid + t * 128;
        v[t] = 0.f;
        if (dd < DDIM) {
            v[t] = x[base + dd] + y[base + dd];
            s += v[t];
        }
    }
    __shared__ float red[4];
    int wid = tid >> 5, lane = tid & 31;
    float ws = warpSum(s);
    if (lane == 0) red[wid] = ws;
    __syncthreads();
    float mean = (red[0] + red[1] + red[2] + red[3]) * (1.0f / DDIM);
    float vs = 0.f;
#pragma unroll
    for (int t = 0; t < 4; t++) {
        int dd = tid + t * 128;
        if (dd < DDIM) {
            float d0 = v[t] - mean;
            vs += d0 * d0;
        }
    }
    __syncthreads();
    float wv = warpSum(vs);
    if (lane == 0) red[wid] = wv;
    __syncthreads();
    float var = (red[0] + red[1] + red[2] + red[3]) * (1.0f / DDIM);
    float rstd = rsqrtf(var + 1e-5f);
#pragma unroll
    for (int t = 0; t < 4; t++) {
        int dd = tid + t * 128;
        if (dd < DDIM) x[base + dd] = (v[t] - mean) * rstd;
    }
}

// -------------- energy ------------------------------------------------------
__global__ void zero_out_kernel(float* __restrict__ out) {
    int i = threadIdx.x;
    if (i < GGG) out[i] = 0.f;
}

__global__ void energy_kernel(const float* __restrict__ hn,
                              const float* __restrict__ Wh2,
                              const int* __restrict__ batch,
                              float* __restrict__ out) {
    int n = (blockIdx.x * blockDim.x + threadIdx.x) >> 5;
    int lane = threadIdx.x & 31;
    if (n >= NN) return;
    float p = 0.f;
#pragma unroll
    for (int t = 0; t < 15; t++) {
        int dd = t * 32 + lane;
        p += hn[(size_t)n * DDIM + dd] * Wh2[dd];
    }
    p = warpSum(p);
    if (lane == 0) atomicAdd(&out[batch[n]], p * (1.0f / AVG_NODES_F));
}

// ------------------------- host orchestration -------------------------------
static void launch_gemm(const float* A, const float* B, float* C,
                        int M, int Ncol, int K, float alpha, int act) {
    dim3 grid((Ncol + BN - 1) / BN, (M + BM - 1) / BM);
    gemm_bf16x3_kernel<<<grid, 256>>>(A, B, C, M, Ncol, K, alpha, act);
}

extern "C" void kernel_launch(void* const* d_in, const int* in_sizes, int n_in,
                              void* d_out, int out_size) {
    const float *pos, *atom_table, *Wdeg, *Wd1, *Wd2, *Wd3, *Wq, *Wk, *Wv,
        *Wsh, *W1, *W2, *W3, *Wo, *Wf1, *Wf2, *Wh1, *Wh2;
    const int *node_atom, *edge_src, *edge_dst, *batch;

    if (in_sizes[1] == NN) {
        pos = (const float*)d_in[0];
        node_atom = (const int*)d_in[1];
        edge_src = (const int*)d_in[2];
        edge_dst = (const int*)d_in[3];
        batch = (const int*)d_in[4];
        atom_table = (const float*)d_in[5];
        Wdeg = (const float*)d_in[6];
        Wd1 = (const float*)d_in[7];
        Wd2 = (const float*)d_in[8];
        Wd3 = (const float*)d_in[9];
        Wq = (const float*)d_in[10];
        Wk = (const float*)d_in[11];
        Wv = (const float*)d_in[12];
        Wsh = (const float*)d_in[13];
        W1 = (const float*)d_in[14];
        W2 = (const float*)d_in[15];
        W3 = (const float*)d_in[16];
        Wo = (const float*)d_in[17];
        Wf1 = (const float*)d_in[18];
        Wf2 = (const float*)d_in[19];
        Wh1 = (const float*)d_in[20];
        Wh2 = (const float*)d_in[21];
    } else {
        pos = (const float*)d_in[0];
        atom_table = (const float*)d_in[1];
        Wdeg = (const float*)d_in[2];
        Wd1 = (const float*)d_in[3];
        Wd2 = (const float*)d_in[4];
        Wd3 = (const float*)d_in[5];
        Wq = (const float*)d_in[6];
        Wk = (const float*)d_in[7];
        Wv = (const float*)d_in[8];
        Wsh = (const float*)d_in[9];
        W1 = (const float*)d_in[10];
        W2 = (const float*)d_in[11];
        W3 = (const float*)d_in[12];
        Wo = (const float*)d_in[13];
        Wf1 = (const float*)d_in[14];
        Wf2 = (const float*)d_in[15];
        Wh1 = (const float*)d_in[16];
        Wh2 = (const float*)d_in[17];
        node_atom = (const int*)d_in[18];
        edge_src = (const int*)d_in[19];
        edge_dst = (const int*)d_in[20];
        batch = (const int*)d_in[21];
    }

    float* buf = nullptr;
    cudaGetSymbolAddress((void**)&buf, g_buf);
    float* wqkv = nullptr;
    cudaGetSymbolAddress((void**)&wqkv, g_wqkv);

    float* sh = buf + O_SH;
    float* rbf = buf + O_RBF;
    float* g0 = buf + O_G0;
    float* gate = buf + O_GATE;
    float* x = buf + O_X;
    float* qkv = buf + O_QKV;
    float* agg = buf + O_AGG;
    float* tmp = buf + O_TMP;
    float* hn = buf + O_HN;
    float* hid = buf + O_HID;
    float* logits = buf + O_LOG;
    float* mbuf = buf + O_M;
    float* den = buf + O_DEN;
    float* eh1 = buf + O_EH1;
    float* eh2 = buf + O_EH2;
    float* out = (float*)d_out;

    const float invAvgDeg = (float)(1.0 / sqrt((double)AVG_DEG_F));

    const int warpBlocks = (EE * 32 + 255) / 256;
    const int ndBlocks = (NN * DDIM + 255) / 256;

    // ---- pack fused qkv weights (once per call) ----
    {
        long long tot = (long long)LLAY * DDIM * QKVS;
        packqkv_kernel<<<(int)((tot + 255) / 256), 256>>>(Wq, Wk, Wv, wqkv);
    }

    // ---- precompute (independent of x) ----
    edge_geom_kernel<<<warpBlocks, 256>>>(pos, edge_src, edge_dst, sh, rbf);

    launch_gemm(rbf, Wd1, eh1, EE, 64, NBB, 1.0f, 1);
    launch_gemm(eh1, Wd2, eh2, EE, 64, 64, 1.0f, 1);
    mlp3_kernel<<<warpBlocks, 256>>>(eh2, Wd3, g0, 1);

    for (int l = 0; l < LLAY; l++) {
        launch_gemm(rbf, W1 + (size_t)l * 128 * 64, eh1, EE, 64, NBB, 1.0f, 1);
        launch_gemm(eh1, W2 + (size_t)l * 64 * 64, eh2, EE, 64, 64, 1.0f, 1);
        mlp3_kernel<<<warpBlocks, 256>>>(eh2, W3 + (size_t)l * 64 * HH,
                                         gate + (size_t)l * EE * HH, HH);
    }

    // ---- node features ----
    embed_kernel<<<ndBlocks, 256>>>(atom_table, node_atom, x);
    deg_kernel<<<warpBlocks, 256>>>(sh, Wdeg, g0, edge_dst, x, invAvgDeg);

    // ---- transformer layers ----
    for (int l = 0; l < LLAY; l++) {
        const float* Wqkv_l = wqkv + (size_t)l * DDIM * QKVS;
        const float* Wo_l = Wo + (size_t)l * DDIM * DDIM;
        const float* Wsh_l = Wsh + (size_t)l * SHN * DDIM;
        const float* Wf1_l = Wf1 + (size_t)l * DDIM * 2 * DDIM;
        const float* Wf2_l = Wf2 + (size_t)l * 2 * DDIM * DDIM;
        const float* gate_l = gate + (size_t)l * EE * HH;

        // fused q|k|v projection: (NN,480) @ (480,1440)
        launch_gemm(x, Wqkv_l, qkv, NN, QKVS, DDIM, 1.0f, 0);

        init_layer_kernel<<<ndBlocks, 256>>>(agg, mbuf, den);
        logits_kernel<<<warpBlocks, 256>>>(qkv, sh, Wsh_l, gate_l,
                                           edge_src, edge_dst, logits, mbuf);
        expden_kernel<<<(EE * HH + 255) / 256, 256>>>(logits, mbuf, den, edge_dst);
        scatter_kernel<<<warpBlocks, 256>>>(logits, den, qkv, edge_src, edge_dst, agg);

        launch_gemm(agg, Wo_l, tmp, NN, DDIM, DDIM, invAvgDeg, 0);
        ln_residual_kernel<<<NN, 128>>>(x, tmp);

        launch_gemm(x, Wf1_l, hid, NN, 2 * DDIM, DDIM, 1.0f, 1);
        launch_gemm(hid, Wf2_l, tmp, NN, DDIM, 2 * DDIM, 1.0f, 0);
        ln_residual_kernel<<<NN, 128>>>(x, tmp);
    }

    // ---- readout ----
    launch_gemm(x, Wh1, hn, NN, DDIM, DDIM, 1.0f, 1);
    zero_out_kernel<<<1, 64>>>(out);
    energy_kernel<<<(NN * 32 + 255) / 256, 256>>>(hn, Wh2, batch, out);
}

// round 15
// speedup vs baseline: 1.0200x; 1.0200x over previous
#include <cuda_runtime.h>
#include <cuda_bf16.h>
#include <math.h>
#include <stdint.h>

// ---------------- problem constants ----------------
#define NN   10000
#define EE   160000
#define GGG  64
#define DDIM 480
#define HH   4
#define LLAY 6
#define DHH  120
#define NBB  128
#define SHN  9
#define QKVS 1440
#define MLPW 448   // 7 fused 64-wide MLP bands

static const float AVG_DEG_F   = 15.57930850982666f;
static const float AVG_NODES_F = 18.03065905448718f;

// ---------------- scratch buffer (static device memory) ---------------------
constexpr size_t SZ_SH   = (size_t)EE * SHN;
constexpr size_t SZ_RBF  = (size_t)EE * NBB;
constexpr size_t SZ_G0   = (size_t)EE;
constexpr size_t SZ_GATE = (size_t)LLAY * EE * HH;
constexpr size_t SZ_ND   = (size_t)NN * DDIM;
constexpr size_t SZ_HID  = (size_t)NN * 2 * DDIM;
constexpr size_t SZ_LOG  = (size_t)EE * HH;
constexpr size_t SZ_NH   = (size_t)NN * HH;
constexpr size_t SZ_EHA  = (size_t)EE * MLPW;

constexpr size_t O_SH   = 0;
constexpr size_t O_RBF  = O_SH   + SZ_SH;
constexpr size_t O_G0   = O_RBF  + SZ_RBF;
constexpr size_t O_GATE = O_G0   + SZ_G0;
constexpr size_t O_X    = O_GATE + SZ_GATE;
constexpr size_t O_QKV  = O_X    + SZ_ND;            // NN x 1440 (q|k|v rows)
constexpr size_t O_AGG  = O_QKV  + (size_t)NN * QKVS;
constexpr size_t O_TMP  = O_AGG  + SZ_ND;
constexpr size_t O_HN   = O_TMP  + SZ_ND;
constexpr size_t O_HID  = O_HN   + SZ_ND;
constexpr size_t O_LOG  = O_HID  + SZ_HID;
constexpr size_t O_M    = O_LOG  + SZ_LOG;
constexpr size_t O_DEN  = O_M    + SZ_NH;
constexpr size_t O_EH1A = O_DEN  + SZ_NH;            // E x 448
constexpr size_t O_EH2A = O_EH1A + SZ_EHA;           // E x 448
constexpr size_t TOTAL_F = O_EH2A + SZ_EHA;

__device__ float g_buf[TOTAL_F];

// packed weights
__device__ float g_wqkv[(size_t)LLAY * DDIM * QKVS];   // (L,480,1440)
__device__ float g_w1all[(size_t)NBB * MLPW];          // (128,448): Wd1|W1[l]
__device__ float g_w2all[(size_t)7 * 64 * 64];         // 7 x (64,64): Wd2|W2[l]

// ---------------- helpers ----------------
__device__ __forceinline__ float warpSum(float v) {
#pragma unroll
    for (int o = 16; o; o >>= 1) v += __shfl_down_sync(0xffffffffu, v, o);
    return v;
}

__device__ __forceinline__ float siluf(float x) {
    return x / (1.0f + expf(-x));
}

__device__ __forceinline__ void atomicMaxFloat(float* addr, float val) {
    int old = __float_as_int(*addr);
    while (__int_as_float(old) < val) {
        int prev = atomicCAS((int*)addr, old, __float_as_int(val));
        if (prev == old) break;
        old = prev;
    }
}

__device__ __forceinline__ void split_pack(float v0, float v1,
                                           uint32_t& uhi, uint32_t& ulo) {
    __nv_bfloat162 h;
    h.x = __float2bfloat16_rn(v0);
    h.y = __float2bfloat16_rn(v1);
    float r0 = v0 - __bfloat162float(h.x);
    float r1 = v1 - __bfloat162float(h.y);
    __nv_bfloat162 l;
    l.x = __float2bfloat16_rn(r0);
    l.y = __float2bfloat16_rn(r1);
    uhi = *reinterpret_cast<uint32_t*>(&h);
    ulo = *reinterpret_cast<uint32_t*>(&l);
}

__device__ __forceinline__ void mma_bf16(float& c0, float& c1, float& c2, float& c3,
                                         uint32_t a0, uint32_t a1, uint32_t a2, uint32_t a3,
                                         uint32_t b0, uint32_t b1) {
    asm volatile(
        "mma.sync.aligned.m16n8k16.row.col.f32.bf16.bf16.f32 "
        "{%0,%1,%2,%3}, {%4,%5,%6,%7}, {%8,%9}, {%0,%1,%2,%3};\n"
        : "+f"(c0), "+f"(c1), "+f"(c2), "+f"(c3)
        : "r"(a0), "r"(a1), "r"(a2), "r"(a3), "r"(b0), "r"(b1));
}

// ---------------- weight packing ---------------------------------------------
__global__ void packqkv_kernel(const float* __restrict__ Wq,
                               const float* __restrict__ Wk,
                               const float* __restrict__ Wv,
                               float* __restrict__ W) {
    long long idx = (long long)blockIdx.x * blockDim.x + threadIdx.x;
    long long tot = (long long)LLAY * DDIM * QKVS;
    if (idx >= tot) return;
    int c = (int)(idx % QKVS);
    long long t = idx / QKVS;
    int k = (int)(t % DDIM);
    int l = (int)(t / DDIM);
    const float* src = (c < DDIM) ? Wq : (c < 2 * DDIM) ? Wk : Wv;
    W[idx] = src[((size_t)l * DDIM + k) * DDIM + (c % DDIM)];
}

__global__ void packw1_kernel(const float* __restrict__ Wd1,
                              const float* __restrict__ W1,
                              float* __restrict__ W1all) {
    int idx = blockIdx.x * blockDim.x + threadIdx.x;
    if (idx >= NBB * MLPW) return;
    int k = idx / MLPW, c = idx % MLPW;
    int b = c >> 6, lc = c & 63;
    W1all[idx] = (b == 0) ? Wd1[k * 64 + lc]
                          : W1[((size_t)(b - 1) * NBB + k) * 64 + lc];
}

__global__ void packw2_kernel(const float* __restrict__ Wd2,
                              const float* __restrict__ W2,
                              float* __restrict__ W2all) {
    int idx = blockIdx.x * blockDim.x + threadIdx.x;
    if (idx >= 7 * 64 * 64) return;
    int b = idx / 4096, r = idx % 4096;
    W2all[idx] = (b == 0) ? Wd2[r] : W2[(size_t)(b - 1) * 4096 + r];
}

// ---------------- edge geometry: sh (E,9) + rbf (E,128) -------------------
__global__ void edge_geom_kernel(const float* __restrict__ pos,
                                 const int* __restrict__ src,
                                 const int* __restrict__ dst,
                                 float* __restrict__ sh,
                                 float* __restrict__ rbf) {
    int e = (blockIdx.x * blockDim.x + threadIdx.x) >> 5;
    int lane = threadIdx.x & 31;
    if (e >= EE) return;
    int s = src[e], d = dst[e];
    float vx = pos[s * 3 + 0] - pos[d * 3 + 0];
    float vy = pos[s * 3 + 1] - pos[d * 3 + 1];
    float vz = pos[s * 3 + 2] - pos[d * 3 + 2];
    float r = sqrtf(vx * vx + vy * vy + vz * vz);
    float rr = r + 1e-12f;
    float x = vx / rr, y = vy / rr, z = vz / rr;
    if (lane == 0) {
        const float s3 = 1.7320508075688772f;
        const float s5 = 2.23606797749979f;
        const float s15 = 3.872983346207417f;
        float* o = sh + (size_t)e * SHN;
        o[0] = 1.0f;
        o[1] = s3 * x;
        o[2] = s3 * y;
        o[3] = s3 * z;
        o[4] = s15 * x * y;
        o[5] = s15 * y * z;
        o[6] = 0.5f * s5 * (3.0f * z * z - 1.0f);
        o[7] = s15 * x * z;
        o[8] = 0.5f * s15 * (x * x - y * y);
    }
    const float width = 5.0f / 128.0f;
    const float cstep = 5.0f / 127.0f;
#pragma unroll
    for (int t = 0; t < 4; t++) {
        int i = t * 32 + lane;
        float c = cstep * (float)i;
        float u = (r - c) / width;
        rbf[(size_t)e * NBB + i] = expf(-u * u);
    }
}

// ---------------- bf16x3 tensor-core GEMM -----------------------------------
// C(M,:) (row stride ldc) = act(alpha * A(M,K; row stride lda) @ B)
// bdiag==0: B is (K, Ncol). bdiag==1: B is array of (K,64) blocks; col-block cb
//           uses A cols [cb*64, cb*64+K) (requires K==64) and B + cb*64*K.
#define BM 128
#define BN 64
#define BK 32
#define K2T (BK / 2)
#define ASTR 136
#define BSTR 72

__global__ __launch_bounds__(256) void gemm_bf16x3_kernel(
    const float* __restrict__ A, const float* __restrict__ B,
    float* __restrict__ C, int M, int Ncol, int K, int lda, int ldc,
    float alpha, int act, int bdiag) {
    __shared__ uint32_t As_hi[K2T][ASTR];
    __shared__ uint32_t As_lo[K2T][ASTR];
    __shared__ uint32_t Bs_hi[K2T][BSTR];
    __shared__ uint32_t Bs_lo[K2T][BSTR];

    const int tid = threadIdx.x;
    const int lane = tid & 31;
    const int w = tid >> 5;
    const int warpM = w & 3;
    const int warpN = w >> 2;
    const int gid = lane >> 2;
    const int tig = lane & 3;

    const int rowBase = blockIdx.y * BM;
    const int colBase = blockIdx.x * BN;

    const int aoff = bdiag ? colBase : 0;                 // A column band
    const float* Bp = bdiag ? (B + (size_t)colBase * K) : B;
    const int bw = bdiag ? BN : Ncol;                     // B row width
    const int bcol = bdiag ? 0 : colBase;                 // B col offset

    float c[2][4][4];
#pragma unroll
    for (int mt = 0; mt < 2; mt++)
#pragma unroll
        for (int nt = 0; nt < 4; nt++)
#pragma unroll
            for (int i = 0; i < 4; i++) c[mt][nt][i] = 0.f;

    const int ar = tid >> 3;          // 0..31
    const int ac = (tid & 7) * 4;     // 0,4,...,28
    const int bk2 = tid >> 4;         // 0..15
    const int bn = (tid & 15) * 4;

    for (int kb = 0; kb < K; kb += BK) {
#pragma unroll
        for (int half = 0; half < 4; half++) {
            int rr = ar + half * 32;
            int gr = rowBase + rr;
            float4 av = make_float4(0.f, 0.f, 0.f, 0.f);
            if (gr < M) av = *(const float4*)&A[(size_t)gr * lda + aoff + kb + ac];
            uint32_t uh, ul;
            split_pack(av.x, av.y, uh, ul);
            As_hi[(ac >> 1) + 0][rr] = uh;
            As_lo[(ac >> 1) + 0][rr] = ul;
            split_pack(av.z, av.w, uh, ul);
            As_hi[(ac >> 1) + 1][rr] = uh;
            As_lo[(ac >> 1) + 1][rr] = ul;
        }
        {
            int gc = colBase + bn;
            float4 b0 = make_float4(0.f, 0.f, 0.f, 0.f);
            float4 b1 = make_float4(0.f, 0.f, 0.f, 0.f);
            if (gc < Ncol) {
                b0 = *(const float4*)&Bp[(size_t)(kb + 2 * bk2) * bw + bcol + bn];
                b1 = *(const float4*)&Bp[(size_t)(kb + 2 * bk2 + 1) * bw + bcol + bn];
            }
            const float v0[4] = {b0.x, b0.y, b0.z, b0.w};
            const float v1[4] = {b1.x, b1.y, b1.z, b1.w};
#pragma unroll
            for (int j = 0; j < 4; j++) {
                uint32_t uh, ul;
                split_pack(v0[j], v1[j], uh, ul);
                Bs_hi[bk2][bn + j] = uh;
                Bs_lo[bk2][bn + j] = ul;
            }
        }
        __syncthreads();

#pragma unroll
        for (int ks = 0; ks < 2; ks++) {
            const int k2b = ks * 8;
            uint32_t ah[2][4], al[2][4], bh[4][2], bl[4][2];
#pragma unroll
            for (int mt = 0; mt < 2; mt++) {
                int m = warpM * 32 + mt * 16 + gid;
                ah[mt][0] = As_hi[k2b + tig][m];
                ah[mt][1] = As_hi[k2b + tig][m + 8];
                ah[mt][2] = As_hi[k2b + tig + 4][m];
                ah[mt][3] = As_hi[k2b + tig + 4][m + 8];
                al[mt][0] = As_lo[k2b + tig][m];
                al[mt][1] = As_lo[k2b + tig][m + 8];
                al[mt][2] = As_lo[k2b + tig + 4][m];
                al[mt][3] = As_lo[k2b + tig + 4][m + 8];
            }
#pragma unroll
            for (int nt = 0; nt < 4; nt++) {
                int n = warpN * 32 + nt * 8 + gid;
                bh[nt][0] = Bs_hi[k2b + tig][n];
                bh[nt][1] = Bs_hi[k2b + tig + 4][n];
                bl[nt][0] = Bs_lo[k2b + tig][n];
                bl[nt][1] = Bs_lo[k2b + tig + 4][n];
            }
#pragma unroll
            for (int mt = 0; mt < 2; mt++)
#pragma unroll
                for (int nt = 0; nt < 4; nt++) {
                    mma_bf16(c[mt][nt][0], c[mt][nt][1], c[mt][nt][2], c[mt][nt][3],
                             ah[mt][0], ah[mt][1], ah[mt][2], ah[mt][3],
                             bh[nt][0], bh[nt][1]);
                    mma_bf16(c[mt][nt][0], c[mt][nt][1], c[mt][nt][2], c[mt][nt][3],
                             ah[mt][0], ah[mt][1], ah[mt][2], ah[mt][3],
                             bl[nt][0], bl[nt][1]);
                    mma_bf16(c[mt][nt][0], c[mt][nt][1], c[mt][nt][2], c[mt][nt][3],
                             al[mt][0], al[mt][1], al[mt][2], al[mt][3],
                             bh[nt][0], bh[nt][1]);
                }
        }
        __syncthreads();
    }

#pragma unroll
    for (int mt = 0; mt < 2; mt++) {
#pragma unroll
        for (int nt = 0; nt < 4; nt++) {
            int gr0 = rowBase + warpM * 32 + mt * 16 + gid;
            int gc0 = colBase + warpN * 32 + nt * 8 + 2 * tig;
#pragma unroll
            for (int i = 0; i < 4; i++) {
                int gr = gr0 + (i >> 1) * 8;
                int gc = gc0 + (i & 1);
                if (gr < M && gc < Ncol) {
                    float v = c[mt][nt][i] * alpha;
                    if (act) v = siluf(v);
                    C[(size_t)gr * ldc + gc] = v;
                }
            }
        }
    }
}

// -------------- fused MLP third layer: g0 + 6 gates from (E,448) ------------
__global__ void mlp3_fused_kernel(const float* __restrict__ H2all,
                                  const float* __restrict__ Wd3,
                                  const float* __restrict__ W3,
                                  float* __restrict__ g0,
                                  float* __restrict__ gate) {
    int e = (blockIdx.x * blockDim.x + threadIdx.x) >> 5;
    int lane = threadIdx.x & 31;
    if (e >= EE) return;
    const float* row = H2all + (size_t)e * MLPW;
    // band 0 -> g0 (OD=1)
    {
        float p = row[lane] * Wd3[lane] + row[32 + lane] * Wd3[lane + 32];
        p = warpSum(p);
        if (lane == 0) g0[e] = p;
    }
    // bands 1..6 -> gate[l] (OD=4)
#pragma unroll
    for (int b = 1; b < 7; b++) {
        float v0 = row[b * 64 + lane];
        float v1 = row[b * 64 + 32 + lane];
        const float* W3l = W3 + (size_t)(b - 1) * 64 * HH;
#pragma unroll
        for (int o = 0; o < HH; o++) {
            float q = v0 * W3l[lane * HH + o] + v1 * W3l[(lane + 32) * HH + o];
            q = warpSum(q);
            if (lane == 0)
                gate[(size_t)(b - 1) * EE * HH + (size_t)e * HH + o] = q;
        }
    }
}

// -------------- x = atom_table[node_atom] ----------------------------------
__global__ void embed_kernel(const float* __restrict__ atom_table,
                             const int* __restrict__ node_atom,
                             float* __restrict__ x) {
    int i = blockIdx.x * blockDim.x + threadIdx.x;
    if (i >= NN * DDIM) return;
    int n = i / DDIM, dd = i - n * DDIM;
    x[i] = atom_table[node_atom[n] * DDIM + dd];
}

// -------------- x += (sh@Wdeg)*g0 / sqrt(AVG_DEG), scattered to dst --------
__global__ void deg_kernel(const float* __restrict__ sh,
                           const float* __restrict__ Wdeg,
                           const float* __restrict__ g0,
                           const int* __restrict__ dst,
                           float* __restrict__ x, float scale) {
    int e = (blockIdx.x * blockDim.x + threadIdx.x) >> 5;
    int lane = threadIdx.x & 31;
    if (e >= EE) return;
    int d = dst[e];
    float shreg[SHN];
#pragma unroll
    for (int i = 0; i < SHN; i++) shreg[i] = sh[(size_t)e * SHN + i];
    float g = g0[e] * scale;
#pragma unroll
    for (int t = 0; t < 15; t++) {
        int dd = t * 32 + lane;
        float val = 0.f;
#pragma unroll
        for (int si = 0; si < SHN; si++) val += shreg[si] * Wdeg[si * DDIM + dd];
        atomicAdd(&x[(size_t)d * DDIM + dd], val * g);
    }
}

// -------------- per-layer init: agg=0, m=-inf, den=0 -----------------------
__global__ void init_layer_kernel(float* __restrict__ agg,
                                  float* __restrict__ m,
                                  float* __restrict__ den) {
    int i = blockIdx.x * blockDim.x + threadIdx.x;
    if (i < NN * DDIM) agg[i] = 0.f;
    if (i < NN * HH) {
        m[i] = __int_as_float(0xff800000);
        den[i] = 0.f;
    }
}

// -------------- logits[e,h] = inv*gate * q[dst]·(k[src]+sh@Wsh) ------------
__global__ void logits_kernel(const float* __restrict__ qkv,
                              const float* __restrict__ sh,
                              const float* __restrict__ Wsh_l,
                              const float* __restrict__ gate_l,
                              const int* __restrict__ src,
                              const int* __restrict__ dst,
                              float* __restrict__ logits,
                              float* __restrict__ m) {
    int e = (blockIdx.x * blockDim.x + threadIdx.x) >> 5;
    int lane = threadIdx.x & 31;
    if (e >= EE) return;
    int s = src[e], d = dst[e];
    float shreg[SHN];
#pragma unroll
    for (int i = 0; i < SHN; i++) shreg[i] = sh[(size_t)e * SHN + i];
    const float* qrow = qkv + (size_t)d * QKVS;
    const float* krow = qkv + (size_t)s * QKVS + DDIM;
    const float inv = 0.09128709291752768f;
#pragma unroll
    for (int h = 0; h < HH; h++) {
        float acc = 0.f;
#pragma unroll
        for (int t = 0; t < 4; t++) {
            int j = t * 32 + lane;
            if (j < DHH) {
                int dd = h * DHH + j;
                float kv = krow[dd];
                float shk = 0.f;
#pragma unroll
                for (int si = 0; si < SHN; si++) shk += shreg[si] * Wsh_l[si * DDIM + dd];
                acc += qrow[dd] * (kv + shk);
            }
        }
        acc = warpSum(acc);
        if (lane == 0) {
            float lg = acc * inv * gate_l[(size_t)e * HH + h];
            logits[(size_t)e * HH + h] = lg;
            atomicMaxFloat(&m[(size_t)d * HH + h], lg);
        }
    }
}

// -------------- a = exp(logit - m[dst]); den[dst] += a ----------------------
__global__ void expden_kernel(float* __restrict__ logits,
                              const float* __restrict__ m,
                              float* __restrict__ den,
                              const int* __restrict__ dst) {
    int i = blockIdx.x * blockDim.x + threadIdx.x;
    if (i >= EE * HH) return;
    int e = i >> 2, h = i & 3;
    int d = dst[e];
    float a = expf(logits[i] - m[d * HH + h]);
    logits[i] = a;
    atomicAdd(&den[d * HH + h], a);
}

// -------------- agg[dst] += (a/den) * v[src] --------------------------------
__global__ void scatter_kernel(const float* __restrict__ a,
                               const float* __restrict__ den,
                               const float* __restrict__ qkv,
                               const int* __restrict__ src,
                               const int* __restrict__ dst,
                               float* __restrict__ agg) {
    int e = (blockIdx.x * blockDim.x + threadIdx.x) >> 5;
    int lane = threadIdx.x & 31;
    if (e >= EE) return;
    int s = src[e], d = dst[e];
    float al[HH];
#pragma unroll
    for (int h = 0; h < HH; h++)
        al[h] = a[(size_t)e * HH + h] / (den[(size_t)d * HH + h] + 1e-12f);
    const float* vrow = qkv + (size_t)s * QKVS + 2 * DDIM;
    float* arow = agg + (size_t)d * DDIM;
#pragma unroll
    for (int t = 0; t < 15; t++) {
        int dd = t * 32 + lane;
        int h = dd / DHH;
        atomicAdd(&arow[dd], al[h] * vrow[dd]);
    }
}

// -------------- x = LayerNorm(x + y), row length 480 ------------------------
__global__ void ln_residual_kernel(float* __restrict__ x,
                                   const float* __restrict__ y) {
    int n = blockIdx.x;
    int tid = threadIdx.x;  // 128
    size_t base = (size_t)n * DDIM;
    float v[4];
    float s = 0.f;
#pragma unroll
    for (int t = 0; t < 4; t++) {
        int dd = tid + t * 128;
        v[t] = 0.f;
        if (dd < DDIM) {
            v[t] = x[base + dd] + y[base + dd];
            s += v[t];
        }
    }
    __shared__ float red[4];
    int wid = tid >> 5, lane = tid & 31;
    float ws = warpSum(s);
    if (lane == 0) red[wid] = ws;
    __syncthreads();
    float mean = (red[0] + red[1] + red[2] + red[3]) * (1.0f / DDIM);
    float vs = 0.f;
#pragma unroll
    for (int t = 0; t < 4; t++) {
        int dd = tid + t * 128;
        if (dd < DDIM) {
            float d0 = v[t] - mean;
            vs += d0 * d0;
        }
    }
    __syncthreads();
    float wv = warpSum(vs);
    if (lane == 0) red[wid] = wv;
    __syncthreads();
    float var = (red[0] + red[1] + red[2] + red[3]) * (1.0f / DDIM);
    float rstd = rsqrtf(var + 1e-5f);
#pragma unroll
    for (int t = 0; t < 4; t++) {
        int dd = tid + t * 128;
        if (dd < DDIM) x[base + dd] = (v[t] - mean) * rstd;
    }
}

// -------------- energy ------------------------------------------------------
__global__ void zero_out_kernel(float* __restrict__ out) {
    int i = threadIdx.x;
    if (i < GGG) out[i] = 0.f;
}

__global__ void energy_kernel(const float* __restrict__ hn,
                              const float* __restrict__ Wh2,
                              const int* __restrict__ batch,
                              float* __restrict__ out) {
    int n = (blockIdx.x * blockDim.x + threadIdx.x) >> 5;
    int lane = threadIdx.x & 31;
    if (n >= NN) return;
    float p = 0.f;
#pragma unroll
    for (int t = 0; t < 15; t++) {
        int dd = t * 32 + lane;
        p += hn[(size_t)n * DDIM + dd] * Wh2[dd];
    }
    p = warpSum(p);
    if (lane == 0) atomicAdd(&out[batch[n]], p * (1.0f / AVG_NODES_F));
}

// ------------------------- host orchestration -------------------------------
static void launch_gemm(const float* A, const float* B, float* C,
                        int M, int Ncol, int K, int lda, int ldc,
                        float alpha, int act, int bdiag) {
    dim3 grid((Ncol + BN - 1) / BN, (M + BM - 1) / BM);
    gemm_bf16x3_kernel<<<grid, 256>>>(A, B, C, M, Ncol, K, lda, ldc,
                                      alpha, act, bdiag);
}

extern "C" void kernel_launch(void* const* d_in, const int* in_sizes, int n_in,
                              void* d_out, int out_size) {
    const float *pos, *atom_table, *Wdeg, *Wd1, *Wd2, *Wd3, *Wq, *Wk, *Wv,
        *Wsh, *W1, *W2, *W3, *Wo, *Wf1, *Wf2, *Wh1, *Wh2;
    const int *node_atom, *edge_src, *edge_dst, *batch;

    if (in_sizes[1] == NN) {
        pos = (const float*)d_in[0];
        node_atom = (const int*)d_in[1];
        edge_src = (const int*)d_in[2];
        edge_dst = (const int*)d_in[3];
        batch = (const int*)d_in[4];
        atom_table = (const float*)d_in[5];
        Wdeg = (const float*)d_in[6];
        Wd1 = (const float*)d_in[7];
        Wd2 = (const float*)d_in[8];
        Wd3 = (const float*)d_in[9];
        Wq = (const float*)d_in[10];
        Wk = (const float*)d_in[11];
        Wv = (const float*)d_in[12];
        Wsh = (const float*)d_in[13];
        W1 = (const float*)d_in[14];
        W2 = (const float*)d_in[15];
        W3 = (const float*)d_in[16];
        Wo = (const float*)d_in[17];
        Wf1 = (const float*)d_in[18];
        Wf2 = (const float*)d_in[19];
        Wh1 = (const float*)d_in[20];
        Wh2 = (const float*)d_in[21];
    } else {
        pos = (const float*)d_in[0];
        atom_table = (const float*)d_in[1];
        Wdeg = (const float*)d_in[2];
        Wd1 = (const float*)d_in[3];
        Wd2 = (const float*)d_in[4];
        Wd3 = (const float*)d_in[5];
        Wq = (const float*)d_in[6];
        Wk = (const float*)d_in[7];
        Wv = (const float*)d_in[8];
        Wsh = (const float*)d_in[9];
        W1 = (const float*)d_in[10];
        W2 = (const float*)d_in[11];
        W3 = (const float*)d_in[12];
        Wo = (const float*)d_in[13];
        Wf1 = (const float*)d_in[14];
        Wf2 = (const float*)d_in[15];
        Wh1 = (const float*)d_in[16];
        Wh2 = (const float*)d_in[17];
        node_atom = (const int*)d_in[18];
        edge_src = (const int*)d_in[19];
        edge_dst = (const int*)d_in[20];
        batch = (const int*)d_in[21];
    }

    float* buf = nullptr;
    cudaGetSymbolAddress((void**)&buf, g_buf);
    float* wqkv = nullptr;
    cudaGetSymbolAddress((void**)&wqkv, g_wqkv);
    float* w1all = nullptr;
    cudaGetSymbolAddress((void**)&w1all, g_w1all);
    float* w2all = nullptr;
    cudaGetSymbolAddress((void**)&w2all, g_w2all);

    float* sh = buf + O_SH;
    float* rbf = buf + O_RBF;
    float* g0 = buf + O_G0;
    float* gate = buf + O_GATE;
    float* x = buf + O_X;
    float* qkv = buf + O_QKV;
    float* agg = buf + O_AGG;
    float* tmp = buf + O_TMP;
    float* hn = buf + O_HN;
    float* hid = buf + O_HID;
    float* logits = buf + O_LOG;
    float* mbuf = buf + O_M;
    float* den = buf + O_DEN;
    float* eh1a = buf + O_EH1A;
    float* eh2a = buf + O_EH2A;
    float* out = (float*)d_out;

    const float invAvgDeg = (float)(1.0 / sqrt((double)AVG_DEG_F));

    const int warpBlocks = (EE * 32 + 255) / 256;
    const int ndBlocks = (NN * DDIM + 255) / 256;

    // ---- pack weights (once per call) ----
    {
        long long tot = (long long)LLAY * DDIM * QKVS;
        packqkv_kernel<<<(int)((tot + 255) / 256), 256>>>(Wq, Wk, Wv, wqkv);
        packw1_kernel<<<(NBB * MLPW + 255) / 256, 256>>>(Wd1, W1, w1all);
        packw2_kernel<<<(7 * 64 * 64 + 255) / 256, 256>>>(Wd2, W2, w2all);
    }

    // ---- edge features (fused 7-way radial MLPs) ----
    edge_geom_kernel<<<warpBlocks, 256>>>(pos, edge_src, edge_dst, sh, rbf);
    launch_gemm(rbf, w1all, eh1a, EE, MLPW, NBB, NBB, MLPW, 1.0f, 1, 0);
    launch_gemm(eh1a, w2all, eh2a, EE, MLPW, 64, MLPW, MLPW, 1.0f, 1, 1);
    mlp3_fused_kernel<<<warpBlocks, 256>>>(eh2a, Wd3, W3, g0, gate);

    // ---- node features ----
    embed_kernel<<<ndBlocks, 256>>>(atom_table, node_atom, x);
    deg_kernel<<<warpBlocks, 256>>>(sh, Wdeg, g0, edge_dst, x, invAvgDeg);

    // ---- transformer layers ----
    for (int l = 0; l < LLAY; l++) {
        const float* Wqkv_l = wqkv + (size_t)l * DDIM * QKVS;
        const float* Wo_l = Wo + (size_t)l * DDIM * DDIM;
        const float* Wsh_l = Wsh + (size_t)l * SHN * DDIM;
        const float* Wf1_l = Wf1 + (size_t)l * DDIM * 2 * DDIM;
        const float* Wf2_l = Wf2 + (size_t)l * 2 * DDIM * DDIM;
        const float* gate_l = gate + (size_t)l * EE * HH;

        launch_gemm(x, Wqkv_l, qkv, NN, QKVS, DDIM, DDIM, QKVS, 1.0f, 0, 0);

        init_layer_kernel<<<ndBlocks, 256>>>(agg, mbuf, den);
        logits_kernel<<<warpBlocks, 256>>>(qkv, sh, Wsh_l, gate_l,
                                           edge_src, edge_dst, logits, mbuf);
        expden_kernel<<<(EE * HH + 255) / 256, 256>>>(logits, mbuf, den, edge_dst);
        scatter_kernel<<<warpBlocks, 256>>>(logits, den, qkv, edge_src, edge_dst, agg);

        launch_gemm(agg, Wo_l, tmp, NN, DDIM, DDIM, DDIM, DDIM, invAvgDeg, 0, 0);
        ln_residual_kernel<<<NN, 128>>>(x, tmp);

        launch_gemm(x, Wf1_l, hid, NN, 2 * DDIM, DDIM, DDIM, 2 * DDIM, 1.0f, 1, 0);
        launch_gemm(hid, Wf2_l, tmp, NN, DDIM, 2 * DDIM, 2 * DDIM, DDIM, 1.0f, 0, 0);
        ln_residual_kernel<<<NN, 128>>>(x, tmp);
    }

    // ---- readout ----
    launch_gemm(x, Wh1, hn, NN, DDIM, DDIM, DDIM, DDIM, 1.0f, 1, 0);
    zero_out_kernel<<<1, 64>>>(out);
    energy_kernel<<<(NN * 32 + 255) / 256, 256>>>(hn, Wh2, batch, out);
}

// round 16
// speedup vs baseline: 1.0271x; 1.0069x over previous
#include <cuda_runtime.h>
#include <cuda_bf16.h>
#include <math.h>
#include <stdint.h>

// ---------------- problem constants ----------------
#define NN   10000
#define EE   160000
#define GGG  64
#define DDIM 480
#define HH   4
#define LLAY 6
#define DHH  120
#define NBB  128
#define SHN  9
#define QKVS 1440
#define MLPW 448   // 7 fused 64-wide MLP bands

static const float AVG_DEG_F   = 15.57930850982666f;
static const float AVG_NODES_F = 18.03065905448718f;

// ---------------- scratch buffer (static device memory) ---------------------
constexpr size_t SZ_SH   = (size_t)EE * SHN;
constexpr size_t SZ_RBF  = (size_t)EE * NBB;
constexpr size_t SZ_G0   = (size_t)EE;
constexpr size_t SZ_GATE = (size_t)LLAY * EE * HH;
constexpr size_t SZ_ND   = (size_t)NN * DDIM;
constexpr size_t SZ_HID  = (size_t)NN * 2 * DDIM;
constexpr size_t SZ_LOG  = (size_t)EE * HH;
constexpr size_t SZ_NH   = (size_t)NN * HH;
constexpr size_t SZ_EHA  = (size_t)EE * MLPW;

constexpr size_t O_SH   = 0;
constexpr size_t O_RBF  = O_SH   + SZ_SH;
constexpr size_t O_G0   = O_RBF  + SZ_RBF;
constexpr size_t O_GATE = O_G0   + SZ_G0;
constexpr size_t O_X    = O_GATE + SZ_GATE;
constexpr size_t O_QKV  = O_X    + SZ_ND;            // NN x 1440 (q|k|v rows)
constexpr size_t O_AGG  = O_QKV  + (size_t)NN * QKVS;
constexpr size_t O_TMP  = O_AGG  + SZ_ND;
constexpr size_t O_HN   = O_TMP  + SZ_ND;
constexpr size_t O_HID  = O_HN   + SZ_ND;
constexpr size_t O_LOG  = O_HID  + SZ_HID;
constexpr size_t O_M    = O_LOG  + SZ_LOG;
constexpr size_t O_DEN  = O_M    + SZ_NH;
constexpr size_t O_EH1A = O_DEN  + SZ_NH;            // E x 448
constexpr size_t O_EH2A = O_EH1A + SZ_EHA;           // E x 448
constexpr size_t TOTAL_F = O_EH2A + SZ_EHA;

__device__ float g_buf[TOTAL_F];

// packed weights
__device__ float g_wqkv[(size_t)LLAY * DDIM * QKVS];   // (L,480,1440)
__device__ float g_w1all[(size_t)NBB * MLPW];          // (128,448): Wd1|W1[l]
__device__ float g_w2all[(size_t)7 * 64 * 64];         // 7 x (64,64): Wd2|W2[l]

// ---------------- helpers ----------------
__device__ __forceinline__ float warpSum(float v) {
#pragma unroll
    for (int o = 16; o; o >>= 1) v += __shfl_down_sync(0xffffffffu, v, o);
    return v;
}

__device__ __forceinline__ float siluf(float x) {
    return x / (1.0f + expf(-x));
}

__device__ __forceinline__ void atomicMaxFloat(float* addr, float val) {
    int old = __float_as_int(*addr);
    while (__int_as_float(old) < val) {
        int prev = atomicCAS((int*)addr, old, __float_as_int(val));
        if (prev == old) break;
        old = prev;
    }
}

__device__ __forceinline__ void split_pack(float v0, float v1,
                                           uint32_t& uhi, uint32_t& ulo) {
    __nv_bfloat162 h;
    h.x = __float2bfloat16_rn(v0);
    h.y = __float2bfloat16_rn(v1);
    float r0 = v0 - __bfloat162float(h.x);
    float r1 = v1 - __bfloat162float(h.y);
    __nv_bfloat162 l;
    l.x = __float2bfloat16_rn(r0);
    l.y = __float2bfloat16_rn(r1);
    uhi = *reinterpret_cast<uint32_t*>(&h);
    ulo = *reinterpret_cast<uint32_t*>(&l);
}

__device__ __forceinline__ void mma_bf16(float& c0, float& c1, float& c2, float& c3,
                                         uint32_t a0, uint32_t a1, uint32_t a2, uint32_t a3,
                                         uint32_t b0, uint32_t b1) {
    asm volatile(
        "mma.sync.aligned.m16n8k16.row.col.f32.bf16.bf16.f32 "
        "{%0,%1,%2,%3}, {%4,%5,%6,%7}, {%8,%9}, {%0,%1,%2,%3};\n"
        : "+f"(c0), "+f"(c1), "+f"(c2), "+f"(c3)
        : "r"(a0), "r"(a1), "r"(a2), "r"(a3), "r"(b0), "r"(b1));
}

#define LDSM4(r, a) \
    asm volatile("ldmatrix.sync.aligned.m8n8.x4.shared.b16 {%0,%1,%2,%3}, [%4];" \
                 : "=r"((r)[0]), "=r"((r)[1]), "=r"((r)[2]), "=r"((r)[3]) \
                 : "r"(a))

// ---------------- weight packing ---------------------------------------------
__global__ void packqkv_kernel(const float* __restrict__ Wq,
                               const float* __restrict__ Wk,
                               const float* __restrict__ Wv,
                               float* __restrict__ W) {
    long long idx = (long long)blockIdx.x * blockDim.x + threadIdx.x;
    long long tot = (long long)LLAY * DDIM * QKVS;
    if (idx >= tot) return;
    int c = (int)(idx % QKVS);
    long long t = idx / QKVS;
    int k = (int)(t % DDIM);
    int l = (int)(t / DDIM);
    const float* src = (c < DDIM) ? Wq : (c < 2 * DDIM) ? Wk : Wv;
    W[idx] = src[((size_t)l * DDIM + k) * DDIM + (c % DDIM)];
}

__global__ void packw1_kernel(const float* __restrict__ Wd1,
                              const float* __restrict__ W1,
                              float* __restrict__ W1all) {
    int idx = blockIdx.x * blockDim.x + threadIdx.x;
    if (idx >= NBB * MLPW) return;
    int k = idx / MLPW, c = idx % MLPW;
    int b = c >> 6, lc = c & 63;
    W1all[idx] = (b == 0) ? Wd1[k * 64 + lc]
                          : W1[((size_t)(b - 1) * NBB + k) * 64 + lc];
}

__global__ void packw2_kernel(const float* __restrict__ Wd2,
                              const float* __restrict__ W2,
                              float* __restrict__ W2all) {
    int idx = blockIdx.x * blockDim.x + threadIdx.x;
    if (idx >= 7 * 64 * 64) return;
    int b = idx / 4096, r = idx % 4096;
    W2all[idx] = (b == 0) ? Wd2[r] : W2[(size_t)(b - 1) * 4096 + r];
}

// ---------------- edge geometry: sh (E,9) + rbf (E,128) -------------------
__global__ void edge_geom_kernel(const float* __restrict__ pos,
                                 const int* __restrict__ src,
                                 const int* __restrict__ dst,
                                 float* __restrict__ sh,
                                 float* __restrict__ rbf) {
    int e = (blockIdx.x * blockDim.x + threadIdx.x) >> 5;
    int lane = threadIdx.x & 31;
    if (e >= EE) return;
    int s = src[e], d = dst[e];
    float vx = pos[s * 3 + 0] - pos[d * 3 + 0];
    float vy = pos[s * 3 + 1] - pos[d * 3 + 1];
    float vz = pos[s * 3 + 2] - pos[d * 3 + 2];
    float r = sqrtf(vx * vx + vy * vy + vz * vz);
    float rr = r + 1e-12f;
    float x = vx / rr, y = vy / rr, z = vz / rr;
    if (lane == 0) {
        const float s3 = 1.7320508075688772f;
        const float s5 = 2.23606797749979f;
        const float s15 = 3.872983346207417f;
        float* o = sh + (size_t)e * SHN;
        o[0] = 1.0f;
        o[1] = s3 * x;
        o[2] = s3 * y;
        o[3] = s3 * z;
        o[4] = s15 * x * y;
        o[5] = s15 * y * z;
        o[6] = 0.5f * s5 * (3.0f * z * z - 1.0f);
        o[7] = s15 * x * z;
        o[8] = 0.5f * s15 * (x * x - y * y);
    }
    const float width = 5.0f / 128.0f;
    const float cstep = 5.0f / 127.0f;
#pragma unroll
    for (int t = 0; t < 4; t++) {
        int i = t * 32 + lane;
        float c = cstep * (float)i;
        float u = (r - c) / width;
        rbf[(size_t)e * NBB + i] = expf(-u * u);
    }
}

// ---------------- bf16x3 tensor-core GEMM -----------------------------------
// C(M,:) (row stride ldc) = act(alpha * A(M,K; row stride lda) @ B)
// bdiag==0: B is (K, Ncol). bdiag==1: B is array of (K,64) blocks; col-block cb
//           uses A cols [cb*64, cb*64+K) (requires K==64) and B + cb*64*K.
// A fragments loaded via ldmatrix from row-major [m][k2] tiles (stride 20).
#define BM 128
#define BN 64
#define BK 32
#define K2T (BK / 2)
#define ASTR2 20    // A tile row stride (uint32): conflict-free ldmatrix
#define BSTR 72

__global__ __launch_bounds__(256) void gemm_bf16x3_kernel(
    const float* __restrict__ A, const float* __restrict__ B,
    float* __restrict__ C, int M, int Ncol, int K, int lda, int ldc,
    float alpha, int act, int bdiag) {
    __shared__ uint32_t As_hi[BM][ASTR2];
    __shared__ uint32_t As_lo[BM][ASTR2];
    __shared__ uint32_t Bs_hi[K2T][BSTR];
    __shared__ uint32_t Bs_lo[K2T][BSTR];

    const int tid = threadIdx.x;
    const int lane = tid & 31;
    const int w = tid >> 5;
    const int warpM = w & 3;
    const int warpN = w >> 2;
    const int gid = lane >> 2;
    const int tig = lane & 3;

    const int rowBase = blockIdx.y * BM;
    const int colBase = blockIdx.x * BN;

    const int aoff = bdiag ? colBase : 0;                 // A column band
    const float* Bp = bdiag ? (B + (size_t)colBase * K) : B;
    const int bw = bdiag ? BN : Ncol;                     // B row width
    const int bcol = bdiag ? 0 : colBase;                 // B col offset

    float c[2][4][4];
#pragma unroll
    for (int mt = 0; mt < 2; mt++)
#pragma unroll
        for (int nt = 0; nt < 4; nt++)
#pragma unroll
            for (int i = 0; i < 4; i++) c[mt][nt][i] = 0.f;

    const int ar = tid >> 3;          // 0..31
    const int ac = (tid & 7) * 4;     // k offset 0,4,...,28
    const int ac2 = (tid & 7) * 2;    // k2 offset (even)
    const int bk2 = tid >> 4;         // 0..15
    const int bn = (tid & 15) * 4;

    // ldmatrix per-lane source addresses (A tile), computed once
    const int lrow = ((lane & 8) ? 8 : 0) + (lane & 7);
    const int lcol = (lane >> 4) * 4;   // 0 or 4 (uint32 idx)
    const uint32_t aHi0 = (uint32_t)__cvta_generic_to_shared(
        &As_hi[warpM * 32 + lrow][lcol]);
    const uint32_t aHi1 = (uint32_t)__cvta_generic_to_shared(
        &As_hi[warpM * 32 + 16 + lrow][lcol]);
    const uint32_t aLo0 = (uint32_t)__cvta_generic_to_shared(
        &As_lo[warpM * 32 + lrow][lcol]);
    const uint32_t aLo1 = (uint32_t)__cvta_generic_to_shared(
        &As_lo[warpM * 32 + 16 + lrow][lcol]);

    for (int kb = 0; kb < K; kb += BK) {
        // ---- A tile: row-major [m][k2], single 8B store per half ----
#pragma unroll
        for (int half = 0; half < 4; half++) {
            int rr = ar + half * 32;
            int gr = rowBase + rr;
            float4 av = make_float4(0.f, 0.f, 0.f, 0.f);
            if (gr < M) av = *(const float4*)&A[(size_t)gr * lda + aoff + kb + ac];
            uint32_t uh0, ul0, uh1, ul1;
            split_pack(av.x, av.y, uh0, ul0);
            split_pack(av.z, av.w, uh1, ul1);
            *(uint2*)&As_hi[rr][ac2] = make_uint2(uh0, uh1);
            *(uint2*)&As_lo[rr][ac2] = make_uint2(ul0, ul1);
        }
        // ---- B tile: [k2][n] (unchanged) ----
        {
            int gc = colBase + bn;
            float4 b0 = make_float4(0.f, 0.f, 0.f, 0.f);
            float4 b1 = make_float4(0.f, 0.f, 0.f, 0.f);
            if (gc < Ncol) {
                b0 = *(const float4*)&Bp[(size_t)(kb + 2 * bk2) * bw + bcol + bn];
                b1 = *(const float4*)&Bp[(size_t)(kb + 2 * bk2 + 1) * bw + bcol + bn];
            }
            const float v0[4] = {b0.x, b0.y, b0.z, b0.w};
            const float v1[4] = {b1.x, b1.y, b1.z, b1.w};
#pragma unroll
            for (int j = 0; j < 4; j++) {
                uint32_t uh, ul;
                split_pack(v0[j], v1[j], uh, ul);
                Bs_hi[bk2][bn + j] = uh;
                Bs_lo[bk2][bn + j] = ul;
            }
        }
        __syncthreads();

#pragma unroll
        for (int ks = 0; ks < 2; ks++) {
            const int k2b = ks * 8;
            uint32_t ah[2][4], al[2][4], bh[4][2], bl[4][2];
            // A fragments: one ldmatrix.x4 per (16-row block, hi/lo)
            LDSM4(ah[0], aHi0 + ks * 32);
            LDSM4(ah[1], aHi1 + ks * 32);
            LDSM4(al[0], aLo0 + ks * 32);
            LDSM4(al[1], aLo1 + ks * 32);
#pragma unroll
            for (int nt = 0; nt < 4; nt++) {
                int n = warpN * 32 + nt * 8 + gid;
                bh[nt][0] = Bs_hi[k2b + tig][n];
                bh[nt][1] = Bs_hi[k2b + tig + 4][n];
                bl[nt][0] = Bs_lo[k2b + tig][n];
                bl[nt][1] = Bs_lo[k2b + tig + 4][n];
            }
#pragma unroll
            for (int mt = 0; mt < 2; mt++)
#pragma unroll
                for (int nt = 0; nt < 4; nt++) {
                    mma_bf16(c[mt][nt][0], c[mt][nt][1], c[mt][nt][2], c[mt][nt][3],
                             ah[mt][0], ah[mt][1], ah[mt][2], ah[mt][3],
                             bh[nt][0], bh[nt][1]);
                    mma_bf16(c[mt][nt][0], c[mt][nt][1], c[mt][nt][2], c[mt][nt][3],
                             ah[mt][0], ah[mt][1], ah[mt][2], ah[mt][3],
                             bl[nt][0], bl[nt][1]);
                    mma_bf16(c[mt][nt][0], c[mt][nt][1], c[mt][nt][2], c[mt][nt][3],
                             al[mt][0], al[mt][1], al[mt][2], al[mt][3],
                             bh[nt][0], bh[nt][1]);
                }
        }
        __syncthreads();
    }

#pragma unroll
    for (int mt = 0; mt < 2; mt++) {
#pragma unroll
        for (int nt = 0; nt < 4; nt++) {
            int gr0 = rowBase + warpM * 32 + mt * 16 + gid;
            int gc0 = colBase + warpN * 32 + nt * 8 + 2 * tig;
#pragma unroll
            for (int i = 0; i < 4; i++) {
                int gr = gr0 + (i >> 1) * 8;
                int gc = gc0 + (i & 1);
                if (gr < M && gc < Ncol) {
                    float v = c[mt][nt][i] * alpha;
                    if (act) v = siluf(v);
                    C[(size_t)gr * ldc + gc] = v;
                }
            }
        }
    }
}

// -------------- fused MLP third layer: g0 + 6 gates from (E,448) ------------
__global__ void mlp3_fused_kernel(const float* __restrict__ H2all,
                                  const float* __restrict__ Wd3,
                                  const float* __restrict__ W3,
                                  float* __restrict__ g0,
                                  float* __restrict__ gate) {
    int e = (blockIdx.x * blockDim.x + threadIdx.x) >> 5;
    int lane = threadIdx.x & 31;
    if (e >= EE) return;
    const float* row = H2all + (size_t)e * MLPW;
    {
        float p = row[lane] * Wd3[lane] + row[32 + lane] * Wd3[lane + 32];
        p = warpSum(p);
        if (lane == 0) g0[e] = p;
    }
#pragma unroll
    for (int b = 1; b < 7; b++) {
        float v0 = row[b * 64 + lane];
        float v1 = row[b * 64 + 32 + lane];
        const float* W3l = W3 + (size_t)(b - 1) * 64 * HH;
#pragma unroll
        for (int o = 0; o < HH; o++) {
            float q = v0 * W3l[lane * HH + o] + v1 * W3l[(lane + 32) * HH + o];
            q = warpSum(q);
            if (lane == 0)
                gate[(size_t)(b - 1) * EE * HH + (size_t)e * HH + o] = q;
        }
    }
}

// -------------- x = atom_table[node_atom] ----------------------------------
__global__ void embed_kernel(const float* __restrict__ atom_table,
                             const int* __restrict__ node_atom,
                             float* __restrict__ x) {
    int i = blockIdx.x * blockDim.x + threadIdx.x;
    if (i >= NN * DDIM) return;
    int n = i / DDIM, dd = i - n * DDIM;
    x[i] = atom_table[node_atom[n] * DDIM + dd];
}

// -------------- x += (sh@Wdeg)*g0 / sqrt(AVG_DEG), scattered to dst --------
__global__ void deg_kernel(const float* __restrict__ sh,
                           const float* __restrict__ Wdeg,
                           const float* __restrict__ g0,
                           const int* __restrict__ dst,
                           float* __restrict__ x, float scale) {
    int e = (blockIdx.x * blockDim.x + threadIdx.x) >> 5;
    int lane = threadIdx.x & 31;
    if (e >= EE) return;
    int d = dst[e];
    float shreg[SHN];
#pragma unroll
    for (int i = 0; i < SHN; i++) shreg[i] = sh[(size_t)e * SHN + i];
    float g = g0[e] * scale;
#pragma unroll
    for (int t = 0; t < 15; t++) {
        int dd = t * 32 + lane;
        float val = 0.f;
#pragma unroll
        for (int si = 0; si < SHN; si++) val += shreg[si] * Wdeg[si * DDIM + dd];
        atomicAdd(&x[(size_t)d * DDIM + dd], val * g);
    }
}

// -------------- per-layer init: agg=0, m=-inf, den=0 -----------------------
__global__ void init_layer_kernel(float* __restrict__ agg,
                                  float* __restrict__ m,
                                  float* __restrict__ den) {
    int i = blockIdx.x * blockDim.x + threadIdx.x;
    if (i < NN * DDIM) agg[i] = 0.f;
    if (i < NN * HH) {
        m[i] = __int_as_float(0xff800000);
        den[i] = 0.f;
    }
}

// -------------- logits[e,h] = inv*gate * q[dst]·(k[src]+sh@Wsh) ------------
__global__ void logits_kernel(const float* __restrict__ qkv,
                              const float* __restrict__ sh,
                              const float* __restrict__ Wsh_l,
                              const float* __restrict__ gate_l,
                              const int* __restrict__ src,
                              const int* __restrict__ dst,
                              float* __restrict__ logits,
                              float* __restrict__ m) {
    int e = (blockIdx.x * blockDim.x + threadIdx.x) >> 5;
    int lane = threadIdx.x & 31;
    if (e >= EE) return;
    int s = src[e], d = dst[e];
    float shreg[SHN];
#pragma unroll
    for (int i = 0; i < SHN; i++) shreg[i] = sh[(size_t)e * SHN + i];
    const float* qrow = qkv + (size_t)d * QKVS;
    const float* krow = qkv + (size_t)s * QKVS + DDIM;
    const float inv = 0.09128709291752768f;
#pragma unroll
    for (int h = 0; h < HH; h++) {
        float acc = 0.f;
#pragma unroll
        for (int t = 0; t < 4; t++) {
            int j = t * 32 + lane;
            if (j < DHH) {
                int dd = h * DHH + j;
                float kv = krow[dd];
                float shk = 0.f;
#pragma unroll
                for (int si = 0; si < SHN; si++) shk += shreg[si] * Wsh_l[si * DDIM + dd];
                acc += qrow[dd] * (kv + shk);
            }
        }
        acc = warpSum(acc);
        if (lane == 0) {
            float lg = acc * inv * gate_l[(size_t)e * HH + h];
            logits[(size_t)e * HH + h] = lg;
            atomicMaxFloat(&m[(size_t)d * HH + h], lg);
        }
    }
}

// -------------- a = exp(logit - m[dst]); den[dst] += a ----------------------
__global__ void expden_kernel(float* __restrict__ logits,
                              const float* __restrict__ m,
                              float* __restrict__ den,
                              const int* __restrict__ dst) {
    int i = blockIdx.x * blockDim.x + threadIdx.x;
    if (i >= EE * HH) return;
    int e = i >> 2, h = i & 3;
    int d = dst[e];
    float a = expf(logits[i] - m[d * HH + h]);
    logits[i] = a;
    atomicAdd(&den[d * HH + h], a);
}

// -------------- agg[dst] += (a/den) * v[src] --------------------------------
__global__ void scatter_kernel(const float* __restrict__ a,
                               const float* __restrict__ den,
                               const float* __restrict__ qkv,
                               const int* __restrict__ src,
                               const int* __restrict__ dst,
                               float* __restrict__ agg) {
    int e = (blockIdx.x * blockDim.x + threadIdx.x) >> 5;
    int lane = threadIdx.x & 31;
    if (e >= EE) return;
    int s = src[e], d = dst[e];
    float al[HH];
#pragma unroll
    for (int h = 0; h < HH; h++)
        al[h] = a[(size_t)e * HH + h] / (den[(size_t)d * HH + h] + 1e-12f);
    const float* vrow = qkv + (size_t)s * QKVS + 2 * DDIM;
    float* arow = agg + (size_t)d * DDIM;
#pragma unroll
    for (int t = 0; t < 15; t++) {
        int dd = t * 32 + lane;
        int h = dd / DHH;
        atomicAdd(&arow[dd], al[h] * vrow[dd]);
    }
}

// -------------- x = LayerNorm(x + y), row length 480 ------------------------
__global__ void ln_residual_kernel(float* __restrict__ x,
                                   const float* __restrict__ y) {
    int n = blockIdx.x;
    int tid = threadIdx.x;  // 128
    size_t base = (size_t)n * DDIM;
    float v[4];
    float s = 0.f;
#pragma unroll
    for (int t = 0; t < 4; t++) {
        int dd = tid + t * 128;
        v[t] = 0.f;
        if (dd < DDIM) {
            v[t] = x[base + dd] + y[base + dd];
            s += v[t];
        }
    }
    __shared__ float red[4];
    int wid = tid >> 5, lane = tid & 31;
    float ws = warpSum(s);
    if (lane == 0) red[wid] = ws;
    __syncthreads();
    float mean = (red[0] + red[1] + red[2] + red[3]) * (1.0f / DDIM);
    float vs = 0.f;
#pragma unroll
    for (int t = 0; t < 4; t++) {
        int dd = tid + t * 128;
        if (dd < DDIM) {
            float d0 = v[t] - mean;
            vs += d0 * d0;
        }
    }
    __syncthreads();
    float wv = warpSum(vs);
    if (lane == 0) red[wid] = wv;
    __syncthreads();
    float var = (red[0] + red[1] + red[2] + red[3]) * (1.0f / DDIM);
    float rstd = rsqrtf(var + 1e-5f);
#pragma unroll
    for (int t = 0; t < 4; t++) {
        int dd = tid + t * 128;
        if (dd < DDIM) x[base + dd] = (v[t] - mean) * rstd;
    }
}

// -------------- energy ------------------------------------------------------
__global__ void zero_out_kernel(float* __restrict__ out) {
    int i = threadIdx.x;
    if (i < GGG) out[i] = 0.f;
}

__global__ void energy_kernel(const float* __restrict__ hn,
                              const float* __restrict__ Wh2,
                              const int* __restrict__ batch,
                              float* __restrict__ out) {
    int n = (blockIdx.x * blockDim.x + threadIdx.x) >> 5;
    int lane = threadIdx.x & 31;
    if (n >= NN) return;
    float p = 0.f;
#pragma unroll
    for (int t = 0; t < 15; t++) {
        int dd = t * 32 + lane;
        p += hn[(size_t)n * DDIM + dd] * Wh2[dd];
    }
    p = warpSum(p);
    if (lane == 0) atomicAdd(&out[batch[n]], p * (1.0f / AVG_NODES_F));
}

// ------------------------- host orchestration -------------------------------
static void launch_gemm(const float* A, const float* B, float* C,
                        int M, int Ncol, int K, int lda, int ldc,
                        float alpha, int act, int bdiag) {
    dim3 grid((Ncol + BN - 1) / BN, (M + BM - 1) / BM);
    gemm_bf16x3_kernel<<<grid, 256>>>(A, B, C, M, Ncol, K, lda, ldc,
                                      alpha, act, bdiag);
}

extern "C" void kernel_launch(void* const* d_in, const int* in_sizes, int n_in,
                              void* d_out, int out_size) {
    const float *pos, *atom_table, *Wdeg, *Wd1, *Wd2, *Wd3, *Wq, *Wk, *Wv,
        *Wsh, *W1, *W2, *W3, *Wo, *Wf1, *Wf2, *Wh1, *Wh2;
    const int *node_atom, *edge_src, *edge_dst, *batch;

    if (in_sizes[1] == NN) {
        pos = (const float*)d_in[0];
        node_atom = (const int*)d_in[1];
        edge_src = (const int*)d_in[2];
        edge_dst = (const int*)d_in[3];
        batch = (const int*)d_in[4];
        atom_table = (const float*)d_in[5];
        Wdeg = (const float*)d_in[6];
        Wd1 = (const float*)d_in[7];
        Wd2 = (const float*)d_in[8];
        Wd3 = (const float*)d_in[9];
        Wq = (const float*)d_in[10];
        Wk = (const float*)d_in[11];
        Wv = (const float*)d_in[12];
        Wsh = (const float*)d_in[13];
        W1 = (const float*)d_in[14];
        W2 = (const float*)d_in[15];
        W3 = (const float*)d_in[16];
        Wo = (const float*)d_in[17];
        Wf1 = (const float*)d_in[18];
        Wf2 = (const float*)d_in[19];
        Wh1 = (const float*)d_in[20];
        Wh2 = (const float*)d_in[21];
    } else {
        pos = (const float*)d_in[0];
        atom_table = (const float*)d_in[1];
        Wdeg = (const float*)d_in[2];
        Wd1 = (const float*)d_in[3];
        Wd2 = (const float*)d_in[4];
        Wd3 = (const float*)d_in[5];
        Wq = (const float*)d_in[6];
        Wk = (const float*)d_in[7];
        Wv = (const float*)d_in[8];
        Wsh = (const float*)d_in[9];
        W1 = (const float*)d_in[10];
        W2 = (const float*)d_in[11];
        W3 = (const float*)d_in[12];
        Wo = (const float*)d_in[13];
        Wf1 = (const float*)d_in[14];
        Wf2 = (const float*)d_in[15];
        Wh1 = (const float*)d_in[16];
        Wh2 = (const float*)d_in[17];
        node_atom = (const int*)d_in[18];
        edge_src = (const int*)d_in[19];
        edge_dst = (const int*)d_in[20];
        batch = (const int*)d_in[21];
    }

    float* buf = nullptr;
    cudaGetSymbolAddress((void**)&buf, g_buf);
    float* wqkv = nullptr;
    cudaGetSymbolAddress((void**)&wqkv, g_wqkv);
    float* w1all = nullptr;
    cudaGetSymbolAddress((void**)&w1all, g_w1all);
    float* w2all = nullptr;
    cudaGetSymbolAddress((void**)&w2all, g_w2all);

    float* sh = buf + O_SH;
    float* rbf = buf + O_RBF;
    float* g0 = buf + O_G0;
    float* gate = buf + O_GATE;
    float* x = buf + O_X;
    float* qkv = buf + O_QKV;
    float* agg = buf + O_AGG;
    float* tmp = buf + O_TMP;
    float* hn = buf + O_HN;
    float* hid = buf + O_HID;
    float* logits = buf + O_LOG;
    float* mbuf = buf + O_M;
    float* den = buf + O_DEN;
    float* eh1a = buf + O_EH1A;
    float* eh2a = buf + O_EH2A;
    float* out = (float*)d_out;

    const float invAvgDeg = (float)(1.0 / sqrt((double)AVG_DEG_F));

    const int warpBlocks = (EE * 32 + 255) / 256;
    const int ndBlocks = (NN * DDIM + 255) / 256;

    // ---- pack weights (once per call) ----
    {
        long long tot = (long long)LLAY * DDIM * QKVS;
        packqkv_kernel<<<(int)((tot + 255) / 256), 256>>>(Wq, Wk, Wv, wqkv);
        packw1_kernel<<<(NBB * MLPW + 255) / 256, 256>>>(Wd1, W1, w1all);
        packw2_kernel<<<(7 * 64 * 64 + 255) / 256, 256>>>(Wd2, W2, w2all);
    }

    // ---- edge features (fused 7-way radial MLPs) ----
    edge_geom_kernel<<<warpBlocks, 256>>>(pos, edge_src, edge_dst, sh, rbf);
    launch_gemm(rbf, w1all, eh1a, EE, MLPW, NBB, NBB, MLPW, 1.0f, 1, 0);
    launch_gemm(eh1a, w2all, eh2a, EE, MLPW, 64, MLPW, MLPW, 1.0f, 1, 1);
    mlp3_fused_kernel<<<warpBlocks, 256>>>(eh2a, Wd3, W3, g0, gate);

    // ---- node features ----
    embed_kernel<<<ndBlocks, 256>>>(atom_table, node_atom, x);
    deg_kernel<<<warpBlocks, 256>>>(sh, Wdeg, g0, edge_dst, x, invAvgDeg);

    // ---- transformer layers ----
    for (int l = 0; l < LLAY; l++) {
        const float* Wqkv_l = wqkv + (size_t)l * DDIM * QKVS;
        const float* Wo_l = Wo + (size_t)l * DDIM * DDIM;
        const float* Wsh_l = Wsh + (size_t)l * SHN * DDIM;
        const float* Wf1_l = Wf1 + (size_t)l * DDIM * 2 * DDIM;
        const float* Wf2_l = Wf2 + (size_t)l * 2 * DDIM * DDIM;
        const float* gate_l = gate + (size_t)l * EE * HH;

        launch_gemm(x, Wqkv_l, qkv, NN, QKVS, DDIM, DDIM, QKVS, 1.0f, 0, 0);

        init_layer_kernel<<<ndBlocks, 256>>>(agg, mbuf, den);
        logits_kernel<<<warpBlocks, 256>>>(qkv, sh, Wsh_l, gate_l,
                                           edge_src, edge_dst, logits, mbuf);
        expden_kernel<<<(EE * HH + 255) / 256, 256>>>(logits, mbuf, den, edge_dst);
        scatter_kernel<<<warpBlocks, 256>>>(logits, den, qkv, edge_src, edge_dst, agg);

        launch_gemm(agg, Wo_l, tmp, NN, DDIM, DDIM, DDIM, DDIM, invAvgDeg, 0, 0);
        ln_residual_kernel<<<NN, 128>>>(x, tmp);

        launch_gemm(x, Wf1_l, hid, NN, 2 * DDIM, DDIM, DDIM, 2 * DDIM, 1.0f, 1, 0);
        launch_gemm(hid, Wf2_l, tmp, NN, DDIM, 2 * DDIM, 2 * DDIM, DDIM, 1.0f, 0, 0);
        ln_residual_kernel<<<NN, 128>>>(x, tmp);
    }

    // ---- readout ----
    launch_gemm(x, Wh1, hn, NN, DDIM, DDIM, DDIM, DDIM, 1.0f, 1, 0);
    zero_out_kernel<<<1, 64>>>(out);
    energy_kernel<<<(NN * 32 + 255) / 256, 256>>>(hn, Wh2, batch, out);
}

// round 17
// speedup vs baseline: 1.0723x; 1.0440x over previous
#include <cuda_runtime.h>
#include <cuda_bf16.h>
#include <math.h>
#include <stdint.h>

// ---------------- problem constants ----------------
#define NN   10000
#define EE   160000
#define GGG  64
#define DDIM 480
#define HH   4
#define LLAY 6
#define DHH  120
#define NBB  128
#define SHN  9
#define QKVS 1440
#define MLPW 448   // 7 fused 64-wide MLP bands

static const float AVG_DEG_F   = 15.57930850982666f;
static const float AVG_NODES_F = 18.03065905448718f;

// ---------------- scratch buffer (static device memory) ---------------------
constexpr size_t SZ_SH   = (size_t)EE * SHN;
constexpr size_t SZ_RBF  = (size_t)EE * NBB;
constexpr size_t SZ_G0   = (size_t)EE;
constexpr size_t SZ_GATE = (size_t)LLAY * EE * HH;
constexpr size_t SZ_ND   = (size_t)NN * DDIM;
constexpr size_t SZ_HID  = (size_t)NN * 2 * DDIM;
constexpr size_t SZ_LOG  = (size_t)EE * HH;
constexpr size_t SZ_NH   = (size_t)NN * HH;
constexpr size_t SZ_EHA  = (size_t)EE * MLPW;

constexpr size_t O_SH   = 0;
constexpr size_t O_RBF  = O_SH   + SZ_SH;
constexpr size_t O_G0   = O_RBF  + SZ_RBF;
constexpr size_t O_GATE = O_G0   + SZ_G0;
constexpr size_t O_X    = O_GATE + SZ_GATE;
constexpr size_t O_QKV  = O_X    + SZ_ND;            // NN x 1440 (q|k|v rows)
constexpr size_t O_AGG  = O_QKV  + (size_t)NN * QKVS;
constexpr size_t O_TMP  = O_AGG  + SZ_ND;
constexpr size_t O_HN   = O_TMP  + SZ_ND;
constexpr size_t O_HID  = O_HN   + SZ_ND;
constexpr size_t O_LOG  = O_HID  + SZ_HID;
constexpr size_t O_M    = O_LOG  + SZ_LOG;
constexpr size_t O_DEN  = O_M    + SZ_NH;
constexpr size_t O_EH1A = O_DEN  + SZ_NH;            // E x 448
constexpr size_t O_EH2A = O_EH1A + SZ_EHA;           // E x 448
constexpr size_t TOTAL_F = O_EH2A + SZ_EHA;

__device__ float g_buf[TOTAL_F];

// packed weights
__device__ float g_wqkv[(size_t)LLAY * DDIM * QKVS];   // (L,480,1440)
__device__ float g_w1all[(size_t)NBB * MLPW];          // (128,448): Wd1|W1[l]
__device__ float g_w2all[(size_t)7 * 64 * 64];         // 7 x (64,64): Wd2|W2[l]

// ---------------- helpers ----------------
__device__ __forceinline__ float warpSum(float v) {
#pragma unroll
    for (int o = 16; o; o >>= 1) v += __shfl_down_sync(0xffffffffu, v, o);
    return v;
}

__device__ __forceinline__ float siluf(float x) {
    return x / (1.0f + expf(-x));
}

__device__ __forceinline__ void atomicMaxFloat(float* addr, float val) {
    int old = __float_as_int(*addr);
    while (__int_as_float(old) < val) {
        int prev = atomicCAS((int*)addr, old, __float_as_int(val));
        if (prev == old) break;
        old = prev;
    }
}

__device__ __forceinline__ void split_pack(float v0, float v1,
                                           uint32_t& uhi, uint32_t& ulo) {
    __nv_bfloat162 h;
    h.x = __float2bfloat16_rn(v0);
    h.y = __float2bfloat16_rn(v1);
    float r0 = v0 - __bfloat162float(h.x);
    float r1 = v1 - __bfloat162float(h.y);
    __nv_bfloat162 l;
    l.x = __float2bfloat16_rn(r0);
    l.y = __float2bfloat16_rn(r1);
    uhi = *reinterpret_cast<uint32_t*>(&h);
    ulo = *reinterpret_cast<uint32_t*>(&l);
}

__device__ __forceinline__ void mma_bf16(float& c0, float& c1, float& c2, float& c3,
                                         uint32_t a0, uint32_t a1, uint32_t a2, uint32_t a3,
                                         uint32_t b0, uint32_t b1) {
    asm volatile(
        "mma.sync.aligned.m16n8k16.row.col.f32.bf16.bf16.f32 "
        "{%0,%1,%2,%3}, {%4,%5,%6,%7}, {%8,%9}, {%0,%1,%2,%3};\n"
        : "+f"(c0), "+f"(c1), "+f"(c2), "+f"(c3)
        : "r"(a0), "r"(a1), "r"(a2), "r"(a3), "r"(b0), "r"(b1));
}

#define LDSM4(r, a) \
    asm volatile("ldmatrix.sync.aligned.m8n8.x4.shared.b16 {%0,%1,%2,%3}, [%4];" \
                 : "=r"((r)[0]), "=r"((r)[1]), "=r"((r)[2]), "=r"((r)[3]) \
                 : "r"(a))

// ---------------- weight packing ---------------------------------------------
__global__ void packqkv_kernel(const float* __restrict__ Wq,
                               const float* __restrict__ Wk,
                               const float* __restrict__ Wv,
                               float* __restrict__ W) {
    long long idx = (long long)blockIdx.x * blockDim.x + threadIdx.x;
    long long tot = (long long)LLAY * DDIM * QKVS;
    if (idx >= tot) return;
    int c = (int)(idx % QKVS);
    long long t = idx / QKVS;
    int k = (int)(t % DDIM);
    int l = (int)(t / DDIM);
    const float* src = (c < DDIM) ? Wq : (c < 2 * DDIM) ? Wk : Wv;
    W[idx] = src[((size_t)l * DDIM + k) * DDIM + (c % DDIM)];
}

__global__ void packw1_kernel(const float* __restrict__ Wd1,
                              const float* __restrict__ W1,
                              float* __restrict__ W1all) {
    int idx = blockIdx.x * blockDim.x + threadIdx.x;
    if (idx >= NBB * MLPW) return;
    int k = idx / MLPW, c = idx % MLPW;
    int b = c >> 6, lc = c & 63;
    W1all[idx] = (b == 0) ? Wd1[k * 64 + lc]
                          : W1[((size_t)(b - 1) * NBB + k) * 64 + lc];
}

__global__ void packw2_kernel(const float* __restrict__ Wd2,
                              const float* __restrict__ W2,
                              float* __restrict__ W2all) {
    int idx = blockIdx.x * blockDim.x + threadIdx.x;
    if (idx >= 7 * 64 * 64) return;
    int b = idx / 4096, r = idx % 4096;
    W2all[idx] = (b == 0) ? Wd2[r] : W2[(size_t)(b - 1) * 4096 + r];
}

// ---------------- edge geometry: sh (E,9) + rbf (E,128) -------------------
__global__ void edge_geom_kernel(const float* __restrict__ pos,
                                 const int* __restrict__ src,
                                 const int* __restrict__ dst,
                                 float* __restrict__ sh,
                                 float* __restrict__ rbf) {
    int e = (blockIdx.x * blockDim.x + threadIdx.x) >> 5;
    int lane = threadIdx.x & 31;
    if (e >= EE) return;
    int s = src[e], d = dst[e];
    float vx = pos[s * 3 + 0] - pos[d * 3 + 0];
    float vy = pos[s * 3 + 1] - pos[d * 3 + 1];
    float vz = pos[s * 3 + 2] - pos[d * 3 + 2];
    float r = sqrtf(vx * vx + vy * vy + vz * vz);
    float rr = r + 1e-12f;
    float x = vx / rr, y = vy / rr, z = vz / rr;
    if (lane == 0) {
        const float s3 = 1.7320508075688772f;
        const float s5 = 2.23606797749979f;
        const float s15 = 3.872983346207417f;
        float* o = sh + (size_t)e * SHN;
        o[0] = 1.0f;
        o[1] = s3 * x;
        o[2] = s3 * y;
        o[3] = s3 * z;
        o[4] = s15 * x * y;
        o[5] = s15 * y * z;
        o[6] = 0.5f * s5 * (3.0f * z * z - 1.0f);
        o[7] = s15 * x * z;
        o[8] = 0.5f * s15 * (x * x - y * y);
    }
    const float width = 5.0f / 128.0f;
    const float cstep = 5.0f / 127.0f;
#pragma unroll
    for (int t = 0; t < 4; t++) {
        int i = t * 32 + lane;
        float c = cstep * (float)i;
        float u = (r - c) / width;
        rbf[(size_t)e * NBB + i] = expf(-u * u);
    }
}

// ---------------- bf16x3 tensor-core GEMM (templated N tile) -----------------
// NT = n-tiles (8 cols each) per warp; CTA tile = 128 x (NT*16).
// bdiag==0: B is (K, Ncol). bdiag==1 (NT==4 only): block-diagonal.
#define BM 128
#define BK 32
#define K2T (BK / 2)
#define ASTR2 20    // A tile row stride (uint32): conflict-free ldmatrix

template <int NT>
__global__ __launch_bounds__(256) void gemm_bf16x3_kernel(
    const float* __restrict__ A, const float* __restrict__ B,
    float* __restrict__ C, int M, int Ncol, int K, int lda, int ldc,
    float alpha, int act, int bdiag) {
    constexpr int BNT = NT * 16;
    constexpr int BSTRT = BNT + 8;
    __shared__ uint32_t As_hi[BM][ASTR2];
    __shared__ uint32_t As_lo[BM][ASTR2];
    __shared__ uint32_t Bs_hi[K2T][BSTRT];
    __shared__ uint32_t Bs_lo[K2T][BSTRT];

    const int tid = threadIdx.x;
    const int lane = tid & 31;
    const int w = tid >> 5;
    const int warpM = w & 3;
    const int warpN = w >> 2;
    const int gid = lane >> 2;
    const int tig = lane & 3;

    const int rowBase = blockIdx.y * BM;
    const int colBase = blockIdx.x * BNT;

    const int aoff = bdiag ? colBase : 0;                 // A column band
    const float* Bp = bdiag ? (B + (size_t)colBase * K) : B;
    const int bw = bdiag ? BNT : Ncol;                    // B row width
    const int bcol = bdiag ? 0 : colBase;                 // B col offset

    float c[2][NT][4];
#pragma unroll
    for (int mt = 0; mt < 2; mt++)
#pragma unroll
        for (int nt = 0; nt < NT; nt++)
#pragma unroll
            for (int i = 0; i < 4; i++) c[mt][nt][i] = 0.f;

    const int ar = tid >> 3;          // 0..31
    const int ac = (tid & 7) * 4;     // k offset 0,4,...,28
    const int ac2 = (tid & 7) * 2;    // k2 offset (even)
    const int bk2 = tid >> 4;         // 0..15
    const int bn = (tid & 15) * 4;

    // ldmatrix per-lane source addresses (A tile), computed once
    const int lrow = ((lane & 8) ? 8 : 0) + (lane & 7);
    const int lcol = (lane >> 4) * 4;   // 0 or 4 (uint32 idx)
    const uint32_t aHi0 = (uint32_t)__cvta_generic_to_shared(
        &As_hi[warpM * 32 + lrow][lcol]);
    const uint32_t aHi1 = (uint32_t)__cvta_generic_to_shared(
        &As_hi[warpM * 32 + 16 + lrow][lcol]);
    const uint32_t aLo0 = (uint32_t)__cvta_generic_to_shared(
        &As_lo[warpM * 32 + lrow][lcol]);
    const uint32_t aLo1 = (uint32_t)__cvta_generic_to_shared(
        &As_lo[warpM * 32 + 16 + lrow][lcol]);

    for (int kb = 0; kb < K; kb += BK) {
        // ---- A tile: row-major [m][k2], single 8B store per half ----
#pragma unroll
        for (int half = 0; half < 4; half++) {
            int rr = ar + half * 32;
            int gr = rowBase + rr;
            float4 av = make_float4(0.f, 0.f, 0.f, 0.f);
            if (gr < M) av = *(const float4*)&A[(size_t)gr * lda + aoff + kb + ac];
            uint32_t uh0, ul0, uh1, ul1;
            split_pack(av.x, av.y, uh0, ul0);
            split_pack(av.z, av.w, uh1, ul1);
            *(uint2*)&As_hi[rr][ac2] = make_uint2(uh0, uh1);
            *(uint2*)&As_lo[rr][ac2] = make_uint2(ul0, ul1);
        }
        // ---- B tile: [k2][n], NT/4 column groups of 64 ----
#pragma unroll
        for (int nn = 0; nn < NT / 4; nn++) {
            int cc = bn + nn * 64;
            int gc = colBase + cc;
            float4 b0 = make_float4(0.f, 0.f, 0.f, 0.f);
            float4 b1 = make_float4(0.f, 0.f, 0.f, 0.f);
            if (gc < Ncol) {
                b0 = *(const float4*)&Bp[(size_t)(kb + 2 * bk2) * bw + bcol + cc];
                b1 = *(const float4*)&Bp[(size_t)(kb + 2 * bk2 + 1) * bw + bcol + cc];
            }
            const float v0[4] = {b0.x, b0.y, b0.z, b0.w};
            const float v1[4] = {b1.x, b1.y, b1.z, b1.w};
#pragma unroll
            for (int j = 0; j < 4; j++) {
                uint32_t uh, ul;
                split_pack(v0[j], v1[j], uh, ul);
                Bs_hi[bk2][cc + j] = uh;
                Bs_lo[bk2][cc + j] = ul;
            }
        }
        __syncthreads();

#pragma unroll
        for (int ks = 0; ks < 2; ks++) {
            const int k2b = ks * 8;
            uint32_t ah[2][4], al[2][4], bh[NT][2], bl[NT][2];
            LDSM4(ah[0], aHi0 + ks * 32);
            LDSM4(ah[1], aHi1 + ks * 32);
            LDSM4(al[0], aLo0 + ks * 32);
            LDSM4(al[1], aLo1 + ks * 32);
#pragma unroll
            for (int nt = 0; nt < NT; nt++) {
                int n = warpN * (NT * 8) + nt * 8 + gid;
                bh[nt][0] = Bs_hi[k2b + tig][n];
                bh[nt][1] = Bs_hi[k2b + tig + 4][n];
                bl[nt][0] = Bs_lo[k2b + tig][n];
                bl[nt][1] = Bs_lo[k2b + tig + 4][n];
            }
#pragma unroll
            for (int mt = 0; mt < 2; mt++)
#pragma unroll
                for (int nt = 0; nt < NT; nt++) {
                    mma_bf16(c[mt][nt][0], c[mt][nt][1], c[mt][nt][2], c[mt][nt][3],
                             ah[mt][0], ah[mt][1], ah[mt][2], ah[mt][3],
                             bh[nt][0], bh[nt][1]);
                    mma_bf16(c[mt][nt][0], c[mt][nt][1], c[mt][nt][2], c[mt][nt][3],
                             ah[mt][0], ah[mt][1], ah[mt][2], ah[mt][3],
                             bl[nt][0], bl[nt][1]);
                    mma_bf16(c[mt][nt][0], c[mt][nt][1], c[mt][nt][2], c[mt][nt][3],
                             al[mt][0], al[mt][1], al[mt][2], al[mt][3],
                             bh[nt][0], bh[nt][1]);
                }
        }
        __syncthreads();
    }

#pragma unroll
    for (int mt = 0; mt < 2; mt++) {
#pragma unroll
        for (int nt = 0; nt < NT; nt++) {
            int gr0 = rowBase + warpM * 32 + mt * 16 + gid;
            int gc0 = colBase + warpN * (NT * 8) + nt * 8 + 2 * tig;
#pragma unroll
            for (int i = 0; i < 4; i++) {
                int gr = gr0 + (i >> 1) * 8;
                int gc = gc0 + (i & 1);
                if (gr < M && gc < Ncol) {
                    float v = c[mt][nt][i] * alpha;
                    if (act) v = siluf(v);
                    C[(size_t)gr * ldc + gc] = v;
                }
            }
        }
    }
}

// -------------- fused MLP third layer: g0 + 6 gates from (E,448) ------------
__global__ void mlp3_fused_kernel(const float* __restrict__ H2all,
                                  const float* __restrict__ Wd3,
                                  const float* __restrict__ W3,
                                  float* __restrict__ g0,
                                  float* __restrict__ gate) {
    int e = (blockIdx.x * blockDim.x + threadIdx.x) >> 5;
    int lane = threadIdx.x & 31;
    if (e >= EE) return;
    const float* row = H2all + (size_t)e * MLPW;
    {
        float p = row[lane] * Wd3[lane] + row[32 + lane] * Wd3[lane + 32];
        p = warpSum(p);
        if (lane == 0) g0[e] = p;
    }
#pragma unroll
    for (int b = 1; b < 7; b++) {
        float v0 = row[b * 64 + lane];
        float v1 = row[b * 64 + 32 + lane];
        const float* W3l = W3 + (size_t)(b - 1) * 64 * HH;
#pragma unroll
        for (int o = 0; o < HH; o++) {
            float q = v0 * W3l[lane * HH + o] + v1 * W3l[(lane + 32) * HH + o];
            q = warpSum(q);
            if (lane == 0)
                gate[(size_t)(b - 1) * EE * HH + (size_t)e * HH + o] = q;
        }
    }
}

// -------------- x = atom_table[node_atom] ----------------------------------
__global__ void embed_kernel(const float* __restrict__ atom_table,
                             const int* __restrict__ node_atom,
                             float* __restrict__ x) {
    int i = blockIdx.x * blockDim.x + threadIdx.x;
    if (i >= NN * DDIM) return;
    int n = i / DDIM, dd = i - n * DDIM;
    x[i] = atom_table[node_atom[n] * DDIM + dd];
}

// -------------- x += (sh@Wdeg)*g0 / sqrt(AVG_DEG), scattered to dst --------
__global__ void deg_kernel(const float* __restrict__ sh,
                           const float* __restrict__ Wdeg,
                           const float* __restrict__ g0,
                           const int* __restrict__ dst,
                           float* __restrict__ x, float scale) {
    int e = (blockIdx.x * blockDim.x + threadIdx.x) >> 5;
    int lane = threadIdx.x & 31;
    if (e >= EE) return;
    int d = dst[e];
    float shreg[SHN];
#pragma unroll
    for (int i = 0; i < SHN; i++) shreg[i] = sh[(size_t)e * SHN + i];
    float g = g0[e] * scale;
#pragma unroll
    for (int t = 0; t < 15; t++) {
        int dd = t * 32 + lane;
        float val = 0.f;
#pragma unroll
        for (int si = 0; si < SHN; si++) val += shreg[si] * Wdeg[si * DDIM + dd];
        atomicAdd(&x[(size_t)d * DDIM + dd], val * g);
    }
}

// -------------- per-layer init: agg=0, m=-inf, den=0 -----------------------
__global__ void init_layer_kernel(float* __restrict__ agg,
                                  float* __restrict__ m,
                                  float* __restrict__ den) {
    int i = blockIdx.x * blockDim.x + threadIdx.x;
    if (i < NN * DDIM) agg[i] = 0.f;
    if (i < NN * HH) {
        m[i] = __int_as_float(0xff800000);
        den[i] = 0.f;
    }
}

// -------------- logits[e,h] = inv*gate * q[dst]·(k[src]+sh@Wsh) ------------
__global__ void logits_kernel(const float* __restrict__ qkv,
                              const float* __restrict__ sh,
                              const float* __restrict__ Wsh_l,
                              const float* __restrict__ gate_l,
                              const int* __restrict__ src,
                              const int* __restrict__ dst,
                              float* __restrict__ logits,
                              float* __restrict__ m) {
    int e = (blockIdx.x * blockDim.x + threadIdx.x) >> 5;
    int lane = threadIdx.x & 31;
    if (e >= EE) return;
    int s = src[e], d = dst[e];
    float shreg[SHN];
#pragma unroll
    for (int i = 0; i < SHN; i++) shreg[i] = sh[(size_t)e * SHN + i];
    const float* qrow = qkv + (size_t)d * QKVS;
    const float* krow = qkv + (size_t)s * QKVS + DDIM;
    const float inv = 0.09128709291752768f;
#pragma unroll
    for (int h = 0; h < HH; h++) {
        float acc = 0.f;
#pragma unroll
        for (int t = 0; t < 4; t++) {
            int j = t * 32 + lane;
            if (j < DHH) {
                int dd = h * DHH + j;
                float kv = krow[dd];
                float shk = 0.f;
#pragma unroll
                for (int si = 0; si < SHN; si++) shk += shreg[si] * Wsh_l[si * DDIM + dd];
                acc += qrow[dd] * (kv + shk);
            }
        }
        acc = warpSum(acc);
        if (lane == 0) {
            float lg = acc * inv * gate_l[(size_t)e * HH + h];
            logits[(size_t)e * HH + h] = lg;
            atomicMaxFloat(&m[(size_t)d * HH + h], lg);
        }
    }
}

// -------------- a = exp(logit - m[dst]); den[dst] += a ----------------------
__global__ void expden_kernel(float* __restrict__ logits,
                              const float* __restrict__ m,
                              float* __restrict__ den,
                              const int* __restrict__ dst) {
    int i = blockIdx.x * blockDim.x + threadIdx.x;
    if (i >= EE * HH) return;
    int e = i >> 2, h = i & 3;
    int d = dst[e];
    float a = expf(logits[i] - m[d * HH + h]);
    logits[i] = a;
    atomicAdd(&den[d * HH + h], a);
}

// -------------- agg[dst] += (a/den) * v[src] --------------------------------
__global__ void scatter_kernel(const float* __restrict__ a,
                               const float* __restrict__ den,
                               const float* __restrict__ qkv,
                               const int* __restrict__ src,
                               const int* __restrict__ dst,
                               float* __restrict__ agg) {
    int e = (blockIdx.x * blockDim.x + threadIdx.x) >> 5;
    int lane = threadIdx.x & 31;
    if (e >= EE) return;
    int s = src[e], d = dst[e];
    float al[HH];
#pragma unroll
    for (int h = 0; h < HH; h++)
        al[h] = a[(size_t)e * HH + h] / (den[(size_t)d * HH + h] + 1e-12f);
    const float* vrow = qkv + (size_t)s * QKVS + 2 * DDIM;
    float* arow = agg + (size_t)d * DDIM;
#pragma unroll
    for (int t = 0; t < 15; t++) {
        int dd = t * 32 + lane;
        int h = dd / DHH;
        atomicAdd(&arow[dd], al[h] * vrow[dd]);
    }
}

// -------------- x = LayerNorm(x + y), row length 480 ------------------------
__global__ void ln_residual_kernel(float* __restrict__ x,
                                   const float* __restrict__ y) {
    int n = blockIdx.x;
    int tid = threadIdx.x;  // 128
    size_t base = (size_t)n * DDIM;
    float v[4];
    float s = 0.f;
#pragma unroll
    for (int t = 0; t < 4; t++) {
        int dd = tid + t * 128;
        v[t] = 0.f;
        if (dd < DDIM) {
            v[t] = x[base + dd] + y[base + dd];
            s += v[t];
        }
    }
    __shared__ float red[4];
    int wid = tid >> 5, lane = tid & 31;
    float ws = warpSum(s);
    if (lane == 0) red[wid] = ws;
    __syncthreads();
    float mean = (red[0] + red[1] + red[2] + red[3]) * (1.0f / DDIM);
    float vs = 0.f;
#pragma unroll
    for (int t = 0; t < 4; t++) {
        int dd = tid + t * 128;
        if (dd < DDIM) {
            float d0 = v[t] - mean;
            vs += d0 * d0;
        }
    }
    __syncthreads();
    float wv = warpSum(vs);
    if (lane == 0) red[wid] = wv;
    __syncthreads();
    float var = (red[0] + red[1] + red[2] + red[3]) * (1.0f / DDIM);
    float rstd = rsqrtf(var + 1e-5f);
#pragma unroll
    for (int t = 0; t < 4; t++) {
        int dd = tid + t * 128;
        if (dd < DDIM) x[base + dd] = (v[t] - mean) * rstd;
    }
}

// -------------- energy ------------------------------------------------------
__global__ void zero_out_kernel(float* __restrict__ out) {
    int i = threadIdx.x;
    if (i < GGG) out[i] = 0.f;
}

__global__ void energy_kernel(const float* __restrict__ hn,
                              const float* __restrict__ Wh2,
                              const int* __restrict__ batch,
                              float* __restrict__ out) {
    int n = (blockIdx.x * blockDim.x + threadIdx.x) >> 5;
    int lane = threadIdx.x & 31;
    if (n >= NN) return;
    float p = 0.f;
#pragma unroll
    for (int t = 0; t < 15; t++) {
        int dd = t * 32 + lane;
        p += hn[(size_t)n * DDIM + dd] * Wh2[dd];
    }
    p = warpSum(p);
    if (lane == 0) atomicAdd(&out[batch[n]], p * (1.0f / AVG_NODES_F));
}

// ------------------------- host orchestration -------------------------------
static void launch_gemm4(const float* A, const float* B, float* C,
                         int M, int Ncol, int K, int lda, int ldc,
                         float alpha, int act, int bdiag) {
    dim3 grid((Ncol + 63) / 64, (M + BM - 1) / BM);
    gemm_bf16x3_kernel<4><<<grid, 256>>>(A, B, C, M, Ncol, K, lda, ldc,
                                         alpha, act, bdiag);
}
static void launch_gemm8(const float* A, const float* B, float* C,
                         int M, int Ncol, int K, int lda, int ldc,
                         float alpha, int act) {
    dim3 grid((Ncol + 127) / 128, (M + BM - 1) / BM);
    gemm_bf16x3_kernel<8><<<grid, 256>>>(A, B, C, M, Ncol, K, lda, ldc,
                                         alpha, act, 0);
}

extern "C" void kernel_launch(void* const* d_in, const int* in_sizes, int n_in,
                              void* d_out, int out_size) {
    const float *pos, *atom_table, *Wdeg, *Wd1, *Wd2, *Wd3, *Wq, *Wk, *Wv,
        *Wsh, *W1, *W2, *W3, *Wo, *Wf1, *Wf2, *Wh1, *Wh2;
    const int *node_atom, *edge_src, *edge_dst, *batch;

    if (in_sizes[1] == NN) {
        pos = (const float*)d_in[0];
        node_atom = (const int*)d_in[1];
        edge_src = (const int*)d_in[2];
        edge_dst = (const int*)d_in[3];
        batch = (const int*)d_in[4];
        atom_table = (const float*)d_in[5];
        Wdeg = (const float*)d_in[6];
        Wd1 = (const float*)d_in[7];
        Wd2 = (const float*)d_in[8];
        Wd3 = (const float*)d_in[9];
        Wq = (const float*)d_in[10];
        Wk = (const float*)d_in[11];
        Wv = (const float*)d_in[12];
        Wsh = (const float*)d_in[13];
        W1 = (const float*)d_in[14];
        W2 = (const float*)d_in[15];
        W3 = (const float*)d_in[16];
        Wo = (const float*)d_in[17];
        Wf1 = (const float*)d_in[18];
        Wf2 = (const float*)d_in[19];
        Wh1 = (const float*)d_in[20];
        Wh2 = (const float*)d_in[21];
    } else {
        pos = (const float*)d_in[0];
        atom_table = (const float*)d_in[1];
        Wdeg = (const float*)d_in[2];
        Wd1 = (const float*)d_in[3];
        Wd2 = (const float*)d_in[4];
        Wd3 = (const float*)d_in[5];
        Wq = (const float*)d_in[6];
        Wk = (const float*)d_in[7];
        Wv = (const float*)d_in[8];
        Wsh = (const float*)d_in[9];
        W1 = (const float*)d_in[10];
        W2 = (const float*)d_in[11];
        W3 = (const float*)d_in[12];
        Wo = (const float*)d_in[13];
        Wf1 = (const float*)d_in[14];
        Wf2 = (const float*)d_in[15];
        Wh1 = (const float*)d_in[16];
        Wh2 = (const float*)d_in[17];
        node_atom = (const int*)d_in[18];
        edge_src = (const int*)d_in[19];
        edge_dst = (const int*)d_in[20];
        batch = (const int*)d_in[21];
    }

    float* buf = nullptr;
    cudaGetSymbolAddress((void**)&buf, g_buf);
    float* wqkv = nullptr;
    cudaGetSymbolAddress((void**)&wqkv, g_wqkv);
    float* w1all = nullptr;
    cudaGetSymbolAddress((void**)&w1all, g_w1all);
    float* w2all = nullptr;
    cudaGetSymbolAddress((void**)&w2all, g_w2all);

    float* sh = buf + O_SH;
    float* rbf = buf + O_RBF;
    float* g0 = buf + O_G0;
    float* gate = buf + O_GATE;
    float* x = buf + O_X;
    float* qkv = buf + O_QKV;
    float* agg = buf + O_AGG;
    float* tmp = buf + O_TMP;
    float* hn = buf + O_HN;
    float* hid = buf + O_HID;
    float* logits = buf + O_LOG;
    float* mbuf = buf + O_M;
    float* den = buf + O_DEN;
    float* eh1a = buf + O_EH1A;
    float* eh2a = buf + O_EH2A;
    float* out = (float*)d_out;

    const float invAvgDeg = (float)(1.0 / sqrt((double)AVG_DEG_F));

    const int warpBlocks = (EE * 32 + 255) / 256;
    const int ndBlocks = (NN * DDIM + 255) / 256;

    // ---- pack weights (once per call) ----
    {
        long long tot = (long long)LLAY * DDIM * QKVS;
        packqkv_kernel<<<(int)((tot + 255) / 256), 256>>>(Wq, Wk, Wv, wqkv);
        packw1_kernel<<<(NBB * MLPW + 255) / 256, 256>>>(Wd1, W1, w1all);
        packw2_kernel<<<(7 * 64 * 64 + 255) / 256, 256>>>(Wd2, W2, w2all);
    }

    // ---- edge features (fused 7-way radial MLPs) ----
    edge_geom_kernel<<<warpBlocks, 256>>>(pos, edge_src, edge_dst, sh, rbf);
    launch_gemm4(rbf, w1all, eh1a, EE, MLPW, NBB, NBB, MLPW, 1.0f, 1, 0);
    launch_gemm4(eh1a, w2all, eh2a, EE, MLPW, 64, MLPW, MLPW, 1.0f, 1, 1);
    mlp3_fused_kernel<<<warpBlocks, 256>>>(eh2a, Wd3, W3, g0, gate);

    // ---- node features ----
    embed_kernel<<<ndBlocks, 256>>>(atom_table, node_atom, x);
    deg_kernel<<<warpBlocks, 256>>>(sh, Wdeg, g0, edge_dst, x, invAvgDeg);

    // ---- transformer layers ----
    for (int l = 0; l < LLAY; l++) {
        const float* Wqkv_l = wqkv + (size_t)l * DDIM * QKVS;
        const float* Wo_l = Wo + (size_t)l * DDIM * DDIM;
        const float* Wsh_l = Wsh + (size_t)l * SHN * DDIM;
        const float* Wf1_l = Wf1 + (size_t)l * DDIM * 2 * DDIM;
        const float* Wf2_l = Wf2 + (size_t)l * 2 * DDIM * DDIM;
        const float* gate_l = gate + (size_t)l * EE * HH;

        launch_gemm8(x, Wqkv_l, qkv, NN, QKVS, DDIM, DDIM, QKVS, 1.0f, 0);

        init_layer_kernel<<<ndBlocks, 256>>>(agg, mbuf, den);
        logits_kernel<<<warpBlocks, 256>>>(qkv, sh, Wsh_l, gate_l,
                                           edge_src, edge_dst, logits, mbuf);
        expden_kernel<<<(EE * HH + 255) / 256, 256>>>(logits, mbuf, den, edge_dst);
        scatter_kernel<<<warpBlocks, 256>>>(logits, den, qkv, edge_src, edge_dst, agg);

        launch_gemm8(agg, Wo_l, tmp, NN, DDIM, DDIM, DDIM, DDIM, invAvgDeg, 0);
        ln_residual_kernel<<<NN, 128>>>(x, tmp);

        launch_gemm8(x, Wf1_l, hid, NN, 2 * DDIM, DDIM, DDIM, 2 * DDIM, 1.0f, 1);
        launch_gemm8(hid, Wf2_l, tmp, NN, DDIM, 2 * DDIM, 2 * DDIM, DDIM, 1.0f, 0);
        ln_residual_kernel<<<NN, 128>>>(x, tmp);
    }

    // ---- readout ----
    launch_gemm8(x, Wh1, hn, NN, DDIM, DDIM, DDIM, DDIM, 1.0f, 1);
    zero_out_kernel<<<1, 64>>>(out);
    energy_kernel<<<(NN * 32 + 255) / 256, 256>>>(hn, Wh2, batch, out);
}